// round 13
// baseline (speedup 1.0000x reference)
#include <cuda_runtime.h>
#include <cuda_fp16.h>
#include <math.h>
#include <cstdint>

// ---------------- problem constants ----------------
#define BB    16
#define TT_   512
#define DD    512
#define COUTN 7
#define DFFN  2048
#define NROW  (BB*TT_)     // 8192
#define NROWG (BB*513)     // 8208
#define NBD   (BB*DD)      // 8192 series for fourier

// output tuple layout: (h, lvl, growth, season) flattened fp32
#define OFF_H      0
#define OFF_LVL    ((size_t)BB*TT_*DD)                 // 4194304
#define OFF_GROWTH (OFF_LVL + (size_t)BB*TT_*COUTN)    // 4251648
#define OFF_SEASON (OFF_GROWTH + (size_t)BB*513*DD)    // 8454144

// ---------------- scratch (__device__ globals; no allocs) ----------------
__device__ float  g_cosT [256*512];
__device__ float  g_sinT [256*512];
__device__ __half g_Bhi[512*512];
__device__ __half g_Blo[512*512];
__device__ __half g_AThi[(size_t)NBD*512];
__device__ __half g_ATlo[(size_t)NBD*512];
__device__ float  g_X[(size_t)NBD*512];      // [bd][0:256)=re, [256:512)=im
__device__ int    g_kidx[16*NBD];
__device__ float  g_ar[16*NBD];
__device__ float  g_ai[16*NBD];
__device__ __half g_res1h[(size_t)NROW*DD];
__device__ __half g_vh[(size_t)NROW*DD];
__device__ __half g_gr[(size_t)NROWG*DD];
__device__ __half g_h1h[(size_t)NROW*DD];
__device__ __half g_ffb[(size_t)NROW*DFFN];
__device__ __half g_ff2h[(size_t)NROW*DD];
__device__ float  g_gp[NROW*COUTN];
__device__ float  g_sp[NROW*COUTN];
// fp16 weights
__device__ __half g_Wih[512*512];
__device__ __half g_Woh[512*512];
__device__ __half g_W1h[2048*512];
__device__ __half g_W2h[512*2048];

// ---------------- common helpers ----------------
__device__ __forceinline__ uint32_t smem_u32(const void* p) {
    uint32_t a;
    asm("{ .reg .u64 t; cvta.to.shared.u64 t, %1; cvt.u32.u64 %0, t; }" : "=r"(a) : "l"(p));
    return a;
}
__device__ __forceinline__ void cp16(uint32_t dst, const void* src) {
    asm volatile("cp.async.cg.shared.global [%0], [%1], 16;"
                 :: "r"(dst), "l"(__cvta_generic_to_global(src)) : "memory");
}
#define CP_COMMIT() asm volatile("cp.async.commit_group;" ::: "memory")
#define CP_WAIT1()  asm volatile("cp.async.wait_group 1;" ::: "memory")

#define LDSM_X4(r0, r1, r2, r3, addr) \
    asm volatile("ldmatrix.sync.aligned.m8n8.x4.shared.b16 {%0,%1,%2,%3}, [%4];" \
        : "=r"(r0), "=r"(r1), "=r"(r2), "=r"(r3) : "r"(addr))

#define MMA_F16(c, a, b) \
    asm volatile("mma.sync.aligned.m16n8k16.row.col.f32.f16.f16.f32 " \
        "{%0,%1,%2,%3}, {%4,%5,%6,%7}, {%8,%9}, {%0,%1,%2,%3};" \
        : "+f"((c)[0]), "+f"((c)[1]), "+f"((c)[2]), "+f"((c)[3]) \
        : "r"((a)[0]), "r"((a)[1]), "r"((a)[2]), "r"((a)[3]), \
          "r"((b)[0]), "r"((b)[1]))

// ============== fp16 HMMA GEMM: C[M,N] = A[M,K] @ W[N,K]^T =============
// block 128x128, K-chunk 64 halves, 8 warps (2x4), cp.async 3-stage, 2 CTA/SM.
#define G_SMEM_DYN (3*32768)

template<bool RELU, bool BIAS, bool HALF_OUT>
__global__ __launch_bounds__(256, 2)
void hgemm(const __half* __restrict__ A, const __half* __restrict__ W,
           const float* __restrict__ bias, float* __restrict__ C,
           __half* __restrict__ Ch, int M, int N, int K)
{
    extern __shared__ char smraw[];
    const uint32_t smem = smem_u32(smraw);
    const int tid  = threadIdx.x;
    const int bm   = blockIdx.y * 128;
    const int bn   = blockIdx.x * 128;
    const int lane = tid & 31;
    const int w    = tid >> 5;
    const int m_base = (w >> 2) * 64;
    const int n_base = (w & 3) * 32;

    int str[4], stg[4];
    #pragma unroll
    for (int i = 0; i < 4; i++) {
        int gid = tid + 256 * i;
        str[i] = gid >> 3;
        stg[i] = gid & 7;
    }

    const int rowA  = m_base + (lane & 15);
    const uint32_t cxA = (uint32_t)(rowA & 7);
    const uint32_t gA  = (uint32_t)(lane >> 4);
    uint32_t rowOffA[4];
    #pragma unroll
    for (int mi = 0; mi < 4; mi++) rowOffA[mi] = (uint32_t)(rowA + mi*16) << 7;

    const uint32_t cxB = (uint32_t)(lane & 7);
    const uint32_t gB  = (uint32_t)((lane >> 3) & 1);
    uint32_t rowOffB[2];
    #pragma unroll
    for (int p = 0; p < 2; p++) {
        int rowB = n_base + p*16 + (lane & 7) + ((lane >> 4) << 3);
        rowOffB[p] = (uint32_t)rowB << 7;
    }

    float acc[4][4][4];
    #pragma unroll
    for (int mi = 0; mi < 4; mi++)
        #pragma unroll
        for (int nj = 0; nj < 4; nj++)
            #pragma unroll
            for (int e = 0; e < 4; e++) acc[mi][nj][e] = 0.f;

    const int nch = K >> 6;

    auto issue = [&](int c) {
        const int k0 = c << 6;
        const uint32_t st  = smem + (uint32_t)(c % 3) * 32768;
        const uint32_t stB = st + 16384;
        #pragma unroll
        for (int i = 0; i < 4; i++) {
            uint32_t off = ((uint32_t)str[i] << 7) + (uint32_t)((stg[i] ^ (str[i] & 7)) << 4);
            int rm = bm + str[i]; if (rm > M - 1) rm = M - 1;
            cp16(st  + off, A + (size_t)rm * K + k0 + stg[i]*8);
            cp16(stB + off, W + (size_t)(bn + str[i]) * K + k0 + stg[i]*8);
        }
        CP_COMMIT();
    };
    auto compute_chunk = [&](int s) {
        const uint32_t stA = smem + (uint32_t)s * 32768;
        const uint32_t stB = stA + 16384;
        #pragma unroll
        for (int k16 = 0; k16 < 4; k16++) {
            uint32_t a[4][4];
            #pragma unroll
            for (int mi = 0; mi < 4; mi++) {
                uint32_t ad = stA + rowOffA[mi] + ((((uint32_t)(k16*2) + gA) ^ cxA) << 4);
                LDSM_X4(a[mi][0], a[mi][1], a[mi][2], a[mi][3], ad);
            }
            uint32_t b[4][2];
            #pragma unroll
            for (int p = 0; p < 2; p++) {
                uint32_t bd = stB + rowOffB[p] + ((((uint32_t)(k16*2) + gB) ^ cxB) << 4);
                LDSM_X4(b[2*p][0], b[2*p][1], b[2*p+1][0], b[2*p+1][1], bd);
            }
            #pragma unroll
            for (int mi = 0; mi < 4; mi++)
                #pragma unroll
                for (int nj = 0; nj < 4; nj++)
                    MMA_F16(acc[mi][nj], a[mi], b[nj]);
        }
    };

    issue(0);
    if (nch > 1) issue(1);

    for (int c = 0; c < nch; c++) {
        CP_WAIT1();
        __syncthreads();
        if (c + 2 < nch) issue(c + 2);
        compute_chunk(c % 3);
    }

    #pragma unroll
    for (int mi = 0; mi < 4; mi++) {
        const int r0 = bm + m_base + mi*16 + (lane >> 2);
        const int r1 = r0 + 8;
        #pragma unroll
        for (int nj = 0; nj < 4; nj++) {
            const int col = bn + n_base + nj*8 + (lane & 3)*2;
            float2 v0 = make_float2(acc[mi][nj][0], acc[mi][nj][1]);
            float2 v1 = make_float2(acc[mi][nj][2], acc[mi][nj][3]);
            if (BIAS) {
                float bx = bias[col], by = bias[col + 1];
                v0.x += bx; v0.y += by; v1.x += bx; v1.y += by;
            }
            if (RELU) {
                v0.x = fmaxf(v0.x, 0.f); v0.y = fmaxf(v0.y, 0.f);
                v1.x = fmaxf(v1.x, 0.f); v1.y = fmaxf(v1.y, 0.f);
            }
            if (HALF_OUT) {
                if (r0 < M) *(__half2*)(Ch + (size_t)r0 * N + col) = __floats2half2_rn(v0.x, v0.y);
                if (r1 < M) *(__half2*)(Ch + (size_t)r1 * N + col) = __floats2half2_rn(v1.x, v1.y);
            } else {
                if (r0 < M) *(float2*)(C + (size_t)r0 * N + col) = v0;
                if (r1 < M) *(float2*)(C + (size_t)r1 * N + col) = v1;
            }
        }
    }
}

// ====== split-fp16 DFT GEMM (R8 config): X = AT @ B^T, 64KB stages =========
#define DFT_SMEM_DYN (3*65536)

__global__ __launch_bounds__(256)
void dft_split_hgemm()
{
    extern __shared__ char smraw[];
    const uint32_t smem = smem_u32(smraw);
    const __half* __restrict__ Ahi = g_AThi;
    const __half* __restrict__ Alo = g_ATlo;
    const __half* __restrict__ Bhi = g_Bhi;
    const __half* __restrict__ Blo = g_Blo;
    const int tid  = threadIdx.x;
    const int bm   = blockIdx.y * 128;
    const int bn   = blockIdx.x * 128;
    const int lane = tid & 31;
    const int w    = tid >> 5;
    const int m_base = (w >> 2) * 64;
    const int n_base = (w & 3) * 32;

    int str[4], stg[4];
    #pragma unroll
    for (int i = 0; i < 4; i++) {
        int gid = tid + 256 * i;
        str[i] = gid >> 3;
        stg[i] = gid & 7;
    }

    const int rowA  = m_base + (lane & 15);
    const uint32_t cxA = (uint32_t)(rowA & 7);
    const uint32_t gA  = (uint32_t)(lane >> 4);
    uint32_t rowOffA[4];
    #pragma unroll
    for (int mi = 0; mi < 4; mi++) rowOffA[mi] = (uint32_t)(rowA + mi*16) << 7;

    const uint32_t cxB = (uint32_t)(lane & 7);
    const uint32_t gB  = (uint32_t)((lane >> 3) & 1);
    uint32_t rowOffB[2];
    #pragma unroll
    for (int p = 0; p < 2; p++) {
        int rowB = n_base + p*16 + (lane & 7) + ((lane >> 4) << 3);
        rowOffB[p] = (uint32_t)rowB << 7;
    }

    float acc[4][4][4];
    #pragma unroll
    for (int mi = 0; mi < 4; mi++)
        #pragma unroll
        for (int nj = 0; nj < 4; nj++)
            #pragma unroll
            for (int e = 0; e < 4; e++) acc[mi][nj][e] = 0.f;

    const int nch = 8;

    auto issue = [&](int c) {
        const int k0 = c << 6;
        const uint32_t st = smem + (uint32_t)(c % 3) * 65536;
        #pragma unroll
        for (int i = 0; i < 4; i++) {
            uint32_t off = ((uint32_t)str[i] << 7) + (uint32_t)((stg[i] ^ (str[i] & 7)) << 4);
            size_t offA = (size_t)(bm + str[i]) * 512 + k0 + stg[i]*8;
            size_t offB = (size_t)(bn + str[i]) * 512 + k0 + stg[i]*8;
            cp16(st + off,         Ahi + offA);
            cp16(st + 16384 + off, Alo + offA);
            cp16(st + 32768 + off, Bhi + offB);
            cp16(st + 49152 + off, Blo + offB);
        }
        CP_COMMIT();
    };
    auto compute_chunk = [&](int s) {
        const uint32_t st = smem + (uint32_t)s * 65536;
        #pragma unroll
        for (int k16 = 0; k16 < 4; k16++) {
            uint32_t aH[4][4], aL[4][4];
            #pragma unroll
            for (int mi = 0; mi < 4; mi++) {
                uint32_t xo = rowOffA[mi] + ((((uint32_t)(k16*2) + gA) ^ cxA) << 4);
                LDSM_X4(aH[mi][0], aH[mi][1], aH[mi][2], aH[mi][3], st + xo);
                LDSM_X4(aL[mi][0], aL[mi][1], aL[mi][2], aL[mi][3], st + 16384 + xo);
            }
            uint32_t bH[4][2], bL[4][2];
            #pragma unroll
            for (int p = 0; p < 2; p++) {
                uint32_t xo = rowOffB[p] + ((((uint32_t)(k16*2) + gB) ^ cxB) << 4);
                LDSM_X4(bH[2*p][0], bH[2*p][1], bH[2*p+1][0], bH[2*p+1][1], st + 32768 + xo);
                LDSM_X4(bL[2*p][0], bL[2*p][1], bL[2*p+1][0], bL[2*p+1][1], st + 49152 + xo);
            }
            #pragma unroll
            for (int mi = 0; mi < 4; mi++)
                #pragma unroll
                for (int nj = 0; nj < 4; nj++) {
                    MMA_F16(acc[mi][nj], aL[mi], bH[nj]);
                    MMA_F16(acc[mi][nj], aH[mi], bL[nj]);
                    MMA_F16(acc[mi][nj], aH[mi], bH[nj]);
                }
        }
    };

    issue(0);
    issue(1);

    for (int c = 0; c < nch; c++) {
        CP_WAIT1();
        __syncthreads();
        if (c + 2 < nch) issue(c + 2);
        compute_chunk(c % 3);
    }

    #pragma unroll
    for (int mi = 0; mi < 4; mi++) {
        const int r0 = bm + m_base + mi*16 + (lane >> 2);
        const int r1 = r0 + 8;
        #pragma unroll
        for (int nj = 0; nj < 4; nj++) {
            const int col = bn + n_base + nj*8 + (lane & 3)*2;
            *(float2*)(g_X + (size_t)r0 * 512 + col) = make_float2(acc[mi][nj][0], acc[mi][nj][1]);
            *(float2*)(g_X + (size_t)r1 * 512 + col) = make_float2(acc[mi][nj][2], acc[mi][nj][3]);
        }
    }
}

// ------- fused prep: transpose/split + basis tables + weight f2h -----------
// blocks [0,4096): transpose res -> AT hi/lo
// blocks [4096,5120): basis tables (cos/sin + DFT basis hi/lo)
// blocks [5120,7680): weight fp32->fp16
__global__ __launch_bounds__(256) void prep_kernel(const float* __restrict__ res,
                                                   const float4* __restrict__ Wi,
                                                   const float4* __restrict__ Wo,
                                                   const float4* __restrict__ W1,
                                                   const float4* __restrict__ W2) {
    int blk = blockIdx.x;
    int tid = threadIdx.x;
    if (blk < 4096) {
        __shared__ float tile[32][33];
        int b  = blk >> 8;
        int d0 = ((blk >> 4) & 15) * 32;
        int t0 = (blk & 15) * 32;
        int x = tid & 31, y = tid >> 5;
        const float* src = res + (size_t)b * 512 * 512;
        #pragma unroll
        for (int i = 0; i < 32; i += 8)
            tile[y + i][x] = src[(size_t)(t0 + y + i) * 512 + d0 + x];
        __syncthreads();
        #pragma unroll
        for (int i = 0; i < 32; i += 8) {
            float v = tile[x][y + i];
            __half hi = __float2half_rn(v);
            size_t idx = (size_t)(b*512 + d0 + y + i) * 512 + t0 + x;
            g_AThi[idx] = hi;
            g_ATlo[idx] = __float2half_rn(v - __half2float(hi));
        }
    } else if (blk < 5120) {
        int e = (blk - 4096) * 256 + tid;   // 0..262143
        int n = e >> 9;
        int t = e & 511;
        int k = n & 255;
        int m = (k * t) & 511;
        float ang = 6.283185307179586f * (float)m * (1.0f/512.0f);
        float s, c;
        sincosf(ang, &s, &c);
        if (n < 256) {
            g_cosT[n*512 + t] = c;
            g_sinT[n*512 + t] = s;
        }
        float val = (n < 256) ? c : -s;
        __half hi = __float2half_rn(val);
        g_Bhi[n*512 + t] = hi;
        g_Blo[n*512 + t] = __float2half_rn(val - __half2float(hi));
    } else {
        int i = (blk - 5120) * 256 + tid;   // 0..655359
        const float4* src; __half2* dst; int off;
        if (i < 65536)       { src = Wi; dst = (__half2*)g_Wih; off = i; }
        else if (i < 131072) { src = Wo; dst = (__half2*)g_Woh; off = i - 65536; }
        else if (i < 393216) { src = W1; dst = (__half2*)g_W1h; off = i - 131072; }
        else                 { src = W2; dst = (__half2*)g_W2h; off = i - 393216; }
        float4 v = src[off];
        __half2 h0 = __floats2half2_rn(v.x, v.y);
        __half2 h1 = __floats2half2_rn(v.z, v.w);
        uint2 pk = make_uint2(*(uint32_t*)&h0, *(uint32_t*)&h1);
        *(uint2*)(dst + 2*off) = pk;
    }
}

// -------- top-16 |X|^2 over k in [1,255]: sorted-lane tournament -----------
__global__ __launch_bounds__(256) void topk_kernel() {
    int warp = threadIdx.x >> 5, lane = threadIdx.x & 31;
    int bd = blockIdx.x * 8 + warp;
    const float* xr = g_X + (size_t)bd*512;
    const float* xi = xr + 256;

    unsigned long long key[8];
    #pragma unroll
    for (int j = 0; j < 8; j++) {
        int k = 1 + lane + 32*j;
        if (k <= 255) {
            float r = xr[k], q = xi[k];
            float m2 = fmaf(r, r, q*q);
            key[j] = ((unsigned long long)__float_as_uint(m2) << 32)
                   | (unsigned long long)(511 - k);
        } else key[j] = 0ull;
    }
    #define CSW(a_, b_) { unsigned long long hi_ = key[a_] > key[b_] ? key[a_] : key[b_]; \
                          unsigned long long lo_ = key[a_] > key[b_] ? key[b_] : key[a_]; \
                          key[a_] = hi_; key[b_] = lo_; }
    CSW(0,1) CSW(2,3) CSW(4,5) CSW(6,7)
    CSW(0,2) CSW(1,3) CSW(4,6) CSW(5,7)
    CSW(1,2) CSW(5,6)
    CSW(0,4) CSW(1,5) CSW(2,6) CSW(3,7)
    CSW(2,4) CSW(3,5)
    CSW(1,2) CSW(3,4) CSW(5,6)
    #undef CSW

    #pragma unroll 1
    for (int r = 0; r < 16; r++) {
        unsigned long long cur = key[0];
        unsigned long long m = cur;
        #pragma unroll
        for (int off = 16; off; off >>= 1) {
            unsigned long long o = __shfl_xor_sync(0xffffffffu, m, off);
            if (o > m) m = o;
        }
        if (cur == m) {
            #pragma unroll
            for (int i = 0; i < 7; i++) key[i] = key[i+1];
            key[7] = 0ull;
        }
        if (lane == 0) {
            int k = 511 - (int)(m & 0xffffffffull);
            g_kidx[r*NBD + bd] = k;
            g_ar[r*NBD + bd] = xr[k] * (2.0f/512.0f);
            g_ai[r*NBD + bd] = xi[k] * (2.0f/512.0f);
        }
    }
}

// ------- season synthesis (4-way rotation interleave) + res1h --------------
__global__ __launch_bounds__(256) void season_kernel(const float* __restrict__ res,
                                                     float* __restrict__ season) {
    int bd = blockIdx.x * 256 + threadIdx.x;
    int tt0 = blockIdx.y * 32;
    int b = bd >> 9, d = bd & 511;

    float acc[32];
    #pragma unroll
    for (int i = 0; i < 32; i++) acc[i] = 0.f;

    for (int j = 0; j < 16; j += 4) {
        float c[4], s[4], cd[4], sd[4], ar[4], ai[4];
        #pragma unroll
        for (int q = 0; q < 4; q++) {
            int   k = g_kidx[(j+q)*NBD + bd];
            ar[q] = g_ar[(j+q)*NBD + bd];
            ai[q] = g_ai[(j+q)*NBD + bd];
            int m = (k * tt0) & 511;
            c[q]  = g_cosT[512 + m];  s[q]  = g_sinT[512 + m];
            cd[q] = g_cosT[512 + k];  sd[q] = g_sinT[512 + k];
        }
        #pragma unroll
        for (int i = 0; i < 32; i++) {
            #pragma unroll
            for (int q = 0; q < 4; q++) {
                acc[i] = fmaf(ar[q], c[q], fmaf(-ai[q], s[q], acc[i]));
                float cn = fmaf(c[q], cd[q], -s[q]*sd[q]);
                s[q] = fmaf(s[q], cd[q], c[q]*sd[q]);
                c[q] = cn;
            }
        }
    }
    #pragma unroll
    for (int i = 0; i < 32; i++) {
        int tt = tt0 + i;
        float v = acc[i];
        season[((size_t)(b*608 + tt))*512 + d] = v;
        if (tt < 512) {
            size_t idx = ((size_t)(b*512 + tt))*512 + d;
            g_res1h[idx] = __float2half_rn(res[idx] - v);
        }
    }
}

// -------- growth EMA as 4-way affine scan (fp16 v input) -------------------
__global__ __launch_bounds__(256) void growth_ema_scan(const float* __restrict__ z0,
                                                       const float* __restrict__ v0g,
                                                       const float* __restrict__ sw_g) {
    int blk = blockIdx.x;
    int b   = blk >> 3;
    int hd0 = (blk & 7) << 6;
    int s   = threadIdx.x & 63;
    int q   = threadIdx.x >> 6;
    int hd  = hd0 + s;
    int h   = hd >> 6;
    float alpha = 1.f / (1.f + expf(-sw_g[h]));
    float oma = 1.f - alpha;
    float A = alpha;
    #pragma unroll
    for (int i = 0; i < 7; i++) A *= A;

    const __half* vcol = g_vh + (size_t)b*512*512 + hd;
    const int t0 = q << 7;

    float prev0 = (q == 0) ? z0[hd] : __half2float(vcol[(size_t)(t0 - 1)*512]);
    float prev = prev0;
    float S = 0.f;
    for (int j = 0; j < 128; j++) {
        float x = __half2float(vcol[(size_t)(t0 + j)*512]);
        S = fmaf(alpha, S, oma * (x - prev));
        prev = x;
    }
    __shared__ float Ss[4][64];
    Ss[q][s] = S;
    __syncthreads();

    float E = v0g[hd];
    for (int p = 0; p < q; p++) E = fmaf(A, E, Ss[p][s]);

    prev = prev0;
    float st = E;
    __half* go = g_gr + ((size_t)(b*513 + 1 + t0))*512 + hd;
    if (q == 0) g_gr[((size_t)(b*513))*512 + hd] = __float2half_rn(E);
    for (int j = 0; j < 128; j++) {
        float x = __half2float(vcol[(size_t)(t0 + j)*512]);
        st = fmaf(alpha, st, oma * (x - prev));
        prev = x;
        go[(size_t)j*512] = __float2half_rn(st);
    }
}

// -------- LN helpers --------
__global__ __launch_bounds__(256) void ln_sub_kernel(const float* __restrict__ growth,
                                                     const float* __restrict__ g,
                                                     const float* __restrict__ be) {
    int row = blockIdx.x;
    int b = row >> 9, t = row & 511;
    const __half* pa = g_res1h + (size_t)row*512;
    const float*  pb = growth + (size_t)(b*513 + t + 1)*512;
    int tid = threadIdx.x;
    float x0 = __half2float(pa[tid])       - pb[tid];
    float x1 = __half2float(pa[tid + 256]) - pb[tid + 256];
    __shared__ float red[18];
    float s = x0 + x1, q = fmaf(x0, x0, x1*x1);
    int lane = tid & 31, warp = tid >> 5;
    #pragma unroll
    for (int o = 16; o; o >>= 1) { s += __shfl_xor_sync(~0u, s, o); q += __shfl_xor_sync(~0u, q, o); }
    if (lane == 0) { red[warp] = s; red[8 + warp] = q; }
    __syncthreads();
    if (tid < 32) {
        s = (tid < 8) ? red[tid] : 0.f;
        q = (tid < 8) ? red[8 + tid] : 0.f;
        #pragma unroll
        for (int o = 4; o; o >>= 1) { s += __shfl_xor_sync(~0u, s, o); q += __shfl_xor_sync(~0u, q, o); }
        if (tid == 0) {
            float mu = s * (1.f/512.f);
            float var = q * (1.f/512.f) - mu*mu;
            red[16] = mu; red[17] = rsqrtf(var + 1e-5f);
        }
    }
    __syncthreads();
    float mu = red[16], r = red[17];
    float h0  = (x0 - mu)*r*g[tid]       + be[tid];
    float h1v = (x1 - mu)*r*g[tid + 256] + be[tid + 256];
    g_h1h[(size_t)row*512 + tid]       = __float2half_rn(h0);
    g_h1h[(size_t)row*512 + tid + 256] = __float2half_rn(h1v);
}

__global__ __launch_bounds__(256) void ln_add_kernel(const float* __restrict__ g,
                                                     const float* __restrict__ be,
                                                     float* __restrict__ out) {
    int row = blockIdx.x;
    const __half* pa = g_h1h  + (size_t)row*512;
    const __half* pb = g_ff2h + (size_t)row*512;
    int tid = threadIdx.x;
    float x0 = __half2float(pa[tid])       + __half2float(pb[tid]);
    float x1 = __half2float(pa[tid + 256]) + __half2float(pb[tid + 256]);
    __shared__ float red[18];
    float s = x0 + x1, q = fmaf(x0, x0, x1*x1);
    int lane = tid & 31, warp = tid >> 5;
    #pragma unroll
    for (int o = 16; o; o >>= 1) { s += __shfl_xor_sync(~0u, s, o); q += __shfl_xor_sync(~0u, q, o); }
    if (lane == 0) { red[warp] = s; red[8 + warp] = q; }
    __syncthreads();
    if (tid < 32) {
        s = (tid < 8) ? red[tid] : 0.f;
        q = (tid < 8) ? red[8 + tid] : 0.f;
        #pragma unroll
        for (int o = 4; o; o >>= 1) { s += __shfl_xor_sync(~0u, s, o); q += __shfl_xor_sync(~0u, q, o); }
        if (tid == 0) {
            float mu = s * (1.f/512.f);
            float var = q * (1.f/512.f) - mu*mu;
            red[16] = mu; red[17] = rsqrtf(var + 1e-5f);
        }
    }
    __syncthreads();
    float mu = red[16], r = red[17];
    float* po = out + (size_t)row*512;
    po[tid]       = (x0 - mu)*r*g[tid]       + be[tid];
    po[tid + 256] = (x1 - mu)*r*g[tid + 256] + be[tid + 256];
}

// -------- gp/sp projections, 4 rows per block ------------------------------
__global__ __launch_bounds__(256) void proj7_kernel(const float* __restrict__ growth,
                                                    const float* __restrict__ season,
                                                    const float* __restrict__ Wg,
                                                    const float* __restrict__ bg,
                                                    const float* __restrict__ Ws,
                                                    const float* __restrict__ bs) {
    int row0 = blockIdx.x * 4;
    int tid = threadIdx.x;
    __shared__ float gx[4][512], sx[4][512];
    #pragma unroll
    for (int rr = 0; rr < 4; rr++) {
        int row = row0 + rr;
        int b = row >> 9, t = row & 511;
        const float* grow = growth + (size_t)(b*513 + t + 1)*512;
        const float* srow = season + (size_t)(b*608 + t)*512;
        for (int i = tid; i < 512; i += 256) { gx[rr][i] = grow[i]; sx[rr][i] = srow[i]; }
    }
    __syncthreads();
    int warp = tid >> 5, lane = tid & 31;
    for (int task = warp; task < 28; task += 8) {
        int rr = task / 7, c = task - rr*7;
        float s1 = 0.f, s2 = 0.f;
        const float* wg = Wg + c*512;
        const float* ws = Ws + c*512;
        for (int i = lane; i < 512; i += 32) {
            s1 = fmaf(gx[rr][i], wg[i], s1);
            s2 = fmaf(sx[rr][i], ws[i], s2);
        }
        #pragma unroll
        for (int o = 16; o; o >>= 1) {
            s1 += __shfl_xor_sync(~0u, s1, o);
            s2 += __shfl_xor_sync(~0u, s2, o);
        }
        if (lane == 0) {
            int row = row0 + rr;
            g_gp[row*7 + c] = s1 + bg[c];
            g_sp[row*7 + c] = s2 + bs[c];
        }
    }
}

// -------- level EMA with aux: warp-parallel affine scan --------
__global__ __launch_bounds__(256) void level_scan_kernel(const float* __restrict__ level,
                                                         const float* __restrict__ sw_l,
                                                         const float* __restrict__ v0_l,
                                                         float* __restrict__ lvl_out) {
    int w = (blockIdx.x * blockDim.x + threadIdx.x) >> 5;
    int lane = threadIdx.x & 31;
    if (w >= BB * COUTN) return;
    int b = w / COUTN, c = w % COUTN;
    float alpha = 1.f / (1.f + expf(-sw_l[c]));
    float oma = 1.f - alpha;
    float a2 = alpha*alpha, a4 = a2*a2, a8 = a4*a4;
    float P16 = a8*a8;

    int base = (b*512 + lane*16)*COUTN + c;
    float u1[16], u2[16];
    #pragma unroll
    for (int j = 0; j < 16; j++) {
        int idx = base + j*COUTN;
        u1[j] = oma * (level[idx] - g_sp[idx]);
        u2[j] = alpha * g_gp[idx];
    }
    float S1 = 0.f, S2 = 0.f;
    #pragma unroll
    for (int j = 0; j < 16; j++) { S1 = fmaf(alpha, S1, u1[j]); S2 = fmaf(alpha, S2, u2[j]); }
    float P = P16;
    #pragma unroll
    for (int d = 1; d < 32; d <<= 1) {
        float Pp  = __shfl_up_sync(~0u, P,  d);
        float S1p = __shfl_up_sync(~0u, S1, d);
        float S2p = __shfl_up_sync(~0u, S2, d);
        if (lane >= d) { S1 = fmaf(P, S1p, S1); S2 = fmaf(P, S2p, S2); P *= Pp; }
    }
    float Px  = __shfl_up_sync(~0u, P,  1);
    float S1x = __shfl_up_sync(~0u, S1, 1);
    float S2x = __shfl_up_sync(~0u, S2, 1);
    if (lane == 0) { Px = 1.f; S1x = 0.f; S2x = 0.f; }
    float s   = fmaf(Px, v0_l[c], S1x);
    float aux = S2x;
    #pragma unroll
    for (int j = 0; j < 16; j++) {
        s   = fmaf(alpha, s,   u1[j]);
        aux = fmaf(alpha, aux, u2[j]);
        lvl_out[base + j*COUTN] = s + aux;
    }
}

// ---------------- launch ----------------
extern "C" void kernel_launch(void* const* d_in, const int* in_sizes, int n_in,
                              void* d_out, int out_size) {
    const float* res   = (const float*)d_in[0];
    const float* level = (const float*)d_in[1];
    const float* Wi    = (const float*)d_in[2];
    const float* bi    = (const float*)d_in[3];
    const float* z0    = (const float*)d_in[4];
    const float* v0_g  = (const float*)d_in[5];
    const float* sw_g  = (const float*)d_in[6];
    const float* Wo    = (const float*)d_in[7];
    const float* bo    = (const float*)d_in[8];
    const float* W1    = (const float*)d_in[9];
    const float* W2    = (const float*)d_in[10];
    const float* g1    = (const float*)d_in[11];
    const float* b1    = (const float*)d_in[12];
    const float* g2    = (const float*)d_in[13];
    const float* b2    = (const float*)d_in[14];
    const float* Wg    = (const float*)d_in[15];
    const float* bg    = (const float*)d_in[16];
    const float* Ws    = (const float*)d_in[17];
    const float* bs    = (const float*)d_in[18];
    const float* v0_l  = (const float*)d_in[19];
    const float* sw_l  = (const float*)d_in[20];
    float* out = (float*)d_out;

    __half *p_res1h, *p_vh, *p_gr, *p_h1h, *p_ffb, *p_ff2h, *p_Wih, *p_Woh, *p_W1h, *p_W2h;
    cudaGetSymbolAddress((void**)&p_res1h, g_res1h);
    cudaGetSymbolAddress((void**)&p_vh,    g_vh);
    cudaGetSymbolAddress((void**)&p_gr,    g_gr);
    cudaGetSymbolAddress((void**)&p_h1h,   g_h1h);
    cudaGetSymbolAddress((void**)&p_ffb,   g_ffb);
    cudaGetSymbolAddress((void**)&p_ff2h,  g_ff2h);
    cudaGetSymbolAddress((void**)&p_Wih,   g_Wih);
    cudaGetSymbolAddress((void**)&p_Woh,   g_Woh);
    cudaGetSymbolAddress((void**)&p_W1h,   g_W1h);
    cudaGetSymbolAddress((void**)&p_W2h,   g_W2h);

    cudaFuncSetAttribute(hgemm<false,true,true>,  cudaFuncAttributeMaxDynamicSharedMemorySize, G_SMEM_DYN);
    cudaFuncSetAttribute(hgemm<false,true,false>, cudaFuncAttributeMaxDynamicSharedMemorySize, G_SMEM_DYN);
    cudaFuncSetAttribute(hgemm<true,false,true>,  cudaFuncAttributeMaxDynamicSharedMemorySize, G_SMEM_DYN);
    cudaFuncSetAttribute(hgemm<false,false,true>, cudaFuncAttributeMaxDynamicSharedMemorySize, G_SMEM_DYN);
    cudaFuncSetAttribute(dft_split_hgemm,         cudaFuncAttributeMaxDynamicSharedMemorySize, DFT_SMEM_DYN);

    float* out_season = out + OFF_SEASON;
    float* out_growth = out + OFF_GROWTH;
    float* out_lvl    = out + OFF_LVL;

    // 1. fused prep (transpose/split + basis + weight f2h)
    prep_kernel<<<7680, 256>>>(res, (const float4*)Wi, (const float4*)Wo,
                               (const float4*)W1, (const float4*)W2);
    // 2. DFT on tensor cores (split-fp16, R8 config)
    dft_split_hgemm<<<dim3(4, 64), 256, DFT_SMEM_DYN>>>();
    // 3. top-16 per (b,d)
    topk_kernel<<<NBD/8, 256>>>();
    // 4. season + res1h
    season_kernel<<<dim3(32, 19), 256>>>(res, out_season);
    // 5. v = res1 @ Wi^T + bi  -> fp16
    hgemm<false,true,true><<<dim3(4, 64), 256, G_SMEM_DYN>>>(p_res1h, p_Wih, bi, nullptr, p_vh, NROW, 512, 512);
    // 6. growth EMA scan (fp16 v)
    growth_ema_scan<<<128, 256>>>(z0, v0_g, sw_g);
    // 7. growth = gr @ Wo^T + bo -> d_out (fp32)
    hgemm<false,true,false><<<dim3(4, 65), 256, G_SMEM_DYN>>>(p_gr, p_Woh, bo, out_growth, nullptr, NROWG, 512, 512);
    // 8. h1 = LN(res1 - growth[:,1:]) -> fp16
    ln_sub_kernel<<<NROW, 256>>>(out_growth, g1, b1);
    // 9. ffb = relu(h1 @ W1^T) -> fp16
    hgemm<true,false,true><<<dim3(16, 64), 256, G_SMEM_DYN>>>(p_h1h, p_W1h, nullptr, nullptr, p_ffb, NROW, DFFN, 512);
    // 10. ff2 = ffb @ W2^T -> fp16
    hgemm<false,false,true><<<dim3(4, 64), 256, G_SMEM_DYN>>>(p_ffb, p_W2h, nullptr, nullptr, p_ff2h, NROW, 512, DFFN);
    // 11. h = LN(h1 + ff2) -> d_out
    ln_add_kernel<<<NROW, 256>>>(g2, b2, out + OFF_H);
    // 12. gp/sp projections (4 rows/block)
    proj7_kernel<<<NROW/4, 256>>>(out_growth, out_season, Wg, bg, Ws, bs);
    // 13. level EMA (warp affine scan) -> d_out
    level_scan_kernel<<<(BB*COUTN*32 + 255)/256, 256>>>(level, sw_l, v0_l, out_lvl);
}

// round 14
// speedup vs baseline: 1.0004x; 1.0004x over previous
#include <cuda_runtime.h>
#include <cuda_fp16.h>
#include <math.h>
#include <cstdint>

// ---------------- problem constants ----------------
#define BB    16
#define TT_   512
#define DD    512
#define COUTN 7
#define DFFN  2048
#define NROW  (BB*TT_)     // 8192
#define NROWG (BB*513)     // 8208
#define NBD   (BB*DD)      // 8192 series for fourier

// output tuple layout: (h, lvl, growth, season) flattened fp32
#define OFF_H      0
#define OFF_LVL    ((size_t)BB*TT_*DD)                 // 4194304
#define OFF_GROWTH (OFF_LVL + (size_t)BB*TT_*COUTN)    // 4251648
#define OFF_SEASON (OFF_GROWTH + (size_t)BB*513*DD)    // 8454144

// ---------------- scratch (__device__ globals; no allocs) ----------------
__device__ float  g_cosT [256*512];
__device__ float  g_sinT [256*512];
__device__ __half g_Bhi[512*512];
__device__ __half g_Blo[512*512];
__device__ __half g_AThi[(size_t)NBD*512];
__device__ __half g_ATlo[(size_t)NBD*512];
__device__ float  g_X[(size_t)NBD*512];      // [bd][0:256)=re, [256:512)=im
__device__ int    g_kidx[16*NBD];
__device__ float  g_ar[16*NBD];
__device__ float  g_ai[16*NBD];
__device__ __half g_res1h[(size_t)NROW*DD];
__device__ __half g_vh[(size_t)NROW*DD];
__device__ __half g_gr[(size_t)NROWG*DD];
__device__ __half g_h1h[(size_t)NROW*DD];
__device__ __half g_ffb[(size_t)NROW*DFFN];
__device__ __half g_ff2h[(size_t)NROW*DD];
__device__ float  g_gp[NROW*COUTN];
__device__ float  g_sp[NROW*COUTN];
// fp16 weights
__device__ __half g_Wih[512*512];
__device__ __half g_Woh[512*512];
__device__ __half g_W1h[2048*512];
__device__ __half g_W2h[512*2048];

// ---------------- common helpers ----------------
__device__ __forceinline__ uint32_t smem_u32(const void* p) {
    uint32_t a;
    asm("{ .reg .u64 t; cvta.to.shared.u64 t, %1; cvt.u32.u64 %0, t; }" : "=r"(a) : "l"(p));
    return a;
}
__device__ __forceinline__ void cp16(uint32_t dst, const void* src) {
    asm volatile("cp.async.cg.shared.global [%0], [%1], 16;"
                 :: "r"(dst), "l"(__cvta_generic_to_global(src)) : "memory");
}
#define CP_COMMIT() asm volatile("cp.async.commit_group;" ::: "memory")
#define CP_WAIT1()  asm volatile("cp.async.wait_group 1;" ::: "memory")

#define LDSM_X4(r0, r1, r2, r3, addr) \
    asm volatile("ldmatrix.sync.aligned.m8n8.x4.shared.b16 {%0,%1,%2,%3}, [%4];" \
        : "=r"(r0), "=r"(r1), "=r"(r2), "=r"(r3) : "r"(addr))

#define MMA_F16(c, a, b) \
    asm volatile("mma.sync.aligned.m16n8k16.row.col.f32.f16.f16.f32 " \
        "{%0,%1,%2,%3}, {%4,%5,%6,%7}, {%8,%9}, {%0,%1,%2,%3};" \
        : "+f"((c)[0]), "+f"((c)[1]), "+f"((c)[2]), "+f"((c)[3]) \
        : "r"((a)[0]), "r"((a)[1]), "r"((a)[2]), "r"((a)[3]), \
          "r"((b)[0]), "r"((b)[1]))

// ============== fp16 HMMA GEMM: C[M,N] = A[M,K] @ W[N,K]^T =============
// block 128x128, K-chunk 64 halves, 8 warps (2x4), cp.async 3-stage, 2 CTA/SM.
#define G_SMEM_DYN (3*32768)

template<bool RELU, bool BIAS, bool HALF_OUT>
__global__ __launch_bounds__(256, 2)
void hgemm(const __half* __restrict__ A, const __half* __restrict__ W,
           const float* __restrict__ bias, float* __restrict__ C,
           __half* __restrict__ Ch, int M, int N, int K)
{
    extern __shared__ char smraw[];
    const uint32_t smem = smem_u32(smraw);
    const int tid  = threadIdx.x;
    const int bm   = blockIdx.y * 128;
    const int bn   = blockIdx.x * 128;
    const int lane = tid & 31;
    const int w    = tid >> 5;
    const int m_base = (w >> 2) * 64;
    const int n_base = (w & 3) * 32;

    int str[4], stg[4];
    #pragma unroll
    for (int i = 0; i < 4; i++) {
        int gid = tid + 256 * i;
        str[i] = gid >> 3;
        stg[i] = gid & 7;
    }

    const int rowA  = m_base + (lane & 15);
    const uint32_t cxA = (uint32_t)(rowA & 7);
    const uint32_t gA  = (uint32_t)(lane >> 4);
    uint32_t rowOffA[4];
    #pragma unroll
    for (int mi = 0; mi < 4; mi++) rowOffA[mi] = (uint32_t)(rowA + mi*16) << 7;

    const uint32_t cxB = (uint32_t)(lane & 7);
    const uint32_t gB  = (uint32_t)((lane >> 3) & 1);
    uint32_t rowOffB[2];
    #pragma unroll
    for (int p = 0; p < 2; p++) {
        int rowB = n_base + p*16 + (lane & 7) + ((lane >> 4) << 3);
        rowOffB[p] = (uint32_t)rowB << 7;
    }

    float acc[4][4][4];
    #pragma unroll
    for (int mi = 0; mi < 4; mi++)
        #pragma unroll
        for (int nj = 0; nj < 4; nj++)
            #pragma unroll
            for (int e = 0; e < 4; e++) acc[mi][nj][e] = 0.f;

    const int nch = K >> 6;

    auto issue = [&](int c) {
        const int k0 = c << 6;
        const uint32_t st  = smem + (uint32_t)(c % 3) * 32768;
        const uint32_t stB = st + 16384;
        #pragma unroll
        for (int i = 0; i < 4; i++) {
            uint32_t off = ((uint32_t)str[i] << 7) + (uint32_t)((stg[i] ^ (str[i] & 7)) << 4);
            int rm = bm + str[i]; if (rm > M - 1) rm = M - 1;
            cp16(st  + off, A + (size_t)rm * K + k0 + stg[i]*8);
            cp16(stB + off, W + (size_t)(bn + str[i]) * K + k0 + stg[i]*8);
        }
        CP_COMMIT();
    };
    auto compute_chunk = [&](int s) {
        const uint32_t stA = smem + (uint32_t)s * 32768;
        const uint32_t stB = stA + 16384;
        #pragma unroll
        for (int k16 = 0; k16 < 4; k16++) {
            uint32_t a[4][4];
            #pragma unroll
            for (int mi = 0; mi < 4; mi++) {
                uint32_t ad = stA + rowOffA[mi] + ((((uint32_t)(k16*2) + gA) ^ cxA) << 4);
                LDSM_X4(a[mi][0], a[mi][1], a[mi][2], a[mi][3], ad);
            }
            uint32_t b[4][2];
            #pragma unroll
            for (int p = 0; p < 2; p++) {
                uint32_t bd = stB + rowOffB[p] + ((((uint32_t)(k16*2) + gB) ^ cxB) << 4);
                LDSM_X4(b[2*p][0], b[2*p][1], b[2*p+1][0], b[2*p+1][1], bd);
            }
            #pragma unroll
            for (int mi = 0; mi < 4; mi++)
                #pragma unroll
                for (int nj = 0; nj < 4; nj++)
                    MMA_F16(acc[mi][nj], a[mi], b[nj]);
        }
    };

    issue(0);
    if (nch > 1) issue(1);

    for (int c = 0; c < nch; c++) {
        CP_WAIT1();
        __syncthreads();
        if (c + 2 < nch) issue(c + 2);
        compute_chunk(c % 3);
    }

    #pragma unroll
    for (int mi = 0; mi < 4; mi++) {
        const int r0 = bm + m_base + mi*16 + (lane >> 2);
        const int r1 = r0 + 8;
        #pragma unroll
        for (int nj = 0; nj < 4; nj++) {
            const int col = bn + n_base + nj*8 + (lane & 3)*2;
            float2 v0 = make_float2(acc[mi][nj][0], acc[mi][nj][1]);
            float2 v1 = make_float2(acc[mi][nj][2], acc[mi][nj][3]);
            if (BIAS) {
                float bx = bias[col], by = bias[col + 1];
                v0.x += bx; v0.y += by; v1.x += bx; v1.y += by;
            }
            if (RELU) {
                v0.x = fmaxf(v0.x, 0.f); v0.y = fmaxf(v0.y, 0.f);
                v1.x = fmaxf(v1.x, 0.f); v1.y = fmaxf(v1.y, 0.f);
            }
            if (HALF_OUT) {
                if (r0 < M) *(__half2*)(Ch + (size_t)r0 * N + col) = __floats2half2_rn(v0.x, v0.y);
                if (r1 < M) *(__half2*)(Ch + (size_t)r1 * N + col) = __floats2half2_rn(v1.x, v1.y);
            } else {
                if (r0 < M) *(float2*)(C + (size_t)r0 * N + col) = v0;
                if (r1 < M) *(float2*)(C + (size_t)r1 * N + col) = v1;
            }
        }
    }
}

// ====== split-fp16 DFT GEMM (R8 config): X = AT @ B^T, 64KB stages =========
#define DFT_SMEM_DYN (3*65536)

__global__ __launch_bounds__(256)
void dft_split_hgemm()
{
    extern __shared__ char smraw[];
    const uint32_t smem = smem_u32(smraw);
    const __half* __restrict__ Ahi = g_AThi;
    const __half* __restrict__ Alo = g_ATlo;
    const __half* __restrict__ Bhi = g_Bhi;
    const __half* __restrict__ Blo = g_Blo;
    const int tid  = threadIdx.x;
    const int bm   = blockIdx.y * 128;
    const int bn   = blockIdx.x * 128;
    const int lane = tid & 31;
    const int w    = tid >> 5;
    const int m_base = (w >> 2) * 64;
    const int n_base = (w & 3) * 32;

    int str[4], stg[4];
    #pragma unroll
    for (int i = 0; i < 4; i++) {
        int gid = tid + 256 * i;
        str[i] = gid >> 3;
        stg[i] = gid & 7;
    }

    const int rowA  = m_base + (lane & 15);
    const uint32_t cxA = (uint32_t)(rowA & 7);
    const uint32_t gA  = (uint32_t)(lane >> 4);
    uint32_t rowOffA[4];
    #pragma unroll
    for (int mi = 0; mi < 4; mi++) rowOffA[mi] = (uint32_t)(rowA + mi*16) << 7;

    const uint32_t cxB = (uint32_t)(lane & 7);
    const uint32_t gB  = (uint32_t)((lane >> 3) & 1);
    uint32_t rowOffB[2];
    #pragma unroll
    for (int p = 0; p < 2; p++) {
        int rowB = n_base + p*16 + (lane & 7) + ((lane >> 4) << 3);
        rowOffB[p] = (uint32_t)rowB << 7;
    }

    float acc[4][4][4];
    #pragma unroll
    for (int mi = 0; mi < 4; mi++)
        #pragma unroll
        for (int nj = 0; nj < 4; nj++)
            #pragma unroll
            for (int e = 0; e < 4; e++) acc[mi][nj][e] = 0.f;

    const int nch = 8;

    auto issue = [&](int c) {
        const int k0 = c << 6;
        const uint32_t st = smem + (uint32_t)(c % 3) * 65536;
        #pragma unroll
        for (int i = 0; i < 4; i++) {
            uint32_t off = ((uint32_t)str[i] << 7) + (uint32_t)((stg[i] ^ (str[i] & 7)) << 4);
            size_t offA = (size_t)(bm + str[i]) * 512 + k0 + stg[i]*8;
            size_t offB = (size_t)(bn + str[i]) * 512 + k0 + stg[i]*8;
            cp16(st + off,         Ahi + offA);
            cp16(st + 16384 + off, Alo + offA);
            cp16(st + 32768 + off, Bhi + offB);
            cp16(st + 49152 + off, Blo + offB);
        }
        CP_COMMIT();
    };
    auto compute_chunk = [&](int s) {
        const uint32_t st = smem + (uint32_t)s * 65536;
        #pragma unroll
        for (int k16 = 0; k16 < 4; k16++) {
            uint32_t aH[4][4], aL[4][4];
            #pragma unroll
            for (int mi = 0; mi < 4; mi++) {
                uint32_t xo = rowOffA[mi] + ((((uint32_t)(k16*2) + gA) ^ cxA) << 4);
                LDSM_X4(aH[mi][0], aH[mi][1], aH[mi][2], aH[mi][3], st + xo);
                LDSM_X4(aL[mi][0], aL[mi][1], aL[mi][2], aL[mi][3], st + 16384 + xo);
            }
            uint32_t bH[4][2], bL[4][2];
            #pragma unroll
            for (int p = 0; p < 2; p++) {
                uint32_t xo = rowOffB[p] + ((((uint32_t)(k16*2) + gB) ^ cxB) << 4);
                LDSM_X4(bH[2*p][0], bH[2*p][1], bH[2*p+1][0], bH[2*p+1][1], st + 32768 + xo);
                LDSM_X4(bL[2*p][0], bL[2*p][1], bL[2*p+1][0], bL[2*p+1][1], st + 49152 + xo);
            }
            #pragma unroll
            for (int mi = 0; mi < 4; mi++)
                #pragma unroll
                for (int nj = 0; nj < 4; nj++) {
                    MMA_F16(acc[mi][nj], aL[mi], bH[nj]);
                    MMA_F16(acc[mi][nj], aH[mi], bL[nj]);
                    MMA_F16(acc[mi][nj], aH[mi], bH[nj]);
                }
        }
    };

    issue(0);
    issue(1);

    for (int c = 0; c < nch; c++) {
        CP_WAIT1();
        __syncthreads();
        if (c + 2 < nch) issue(c + 2);
        compute_chunk(c % 3);
    }

    #pragma unroll
    for (int mi = 0; mi < 4; mi++) {
        const int r0 = bm + m_base + mi*16 + (lane >> 2);
        const int r1 = r0 + 8;
        #pragma unroll
        for (int nj = 0; nj < 4; nj++) {
            const int col = bn + n_base + nj*8 + (lane & 3)*2;
            *(float2*)(g_X + (size_t)r0 * 512 + col) = make_float2(acc[mi][nj][0], acc[mi][nj][1]);
            *(float2*)(g_X + (size_t)r1 * 512 + col) = make_float2(acc[mi][nj][2], acc[mi][nj][3]);
        }
    }
}

// ------- fused prep: transpose/split + basis tables + weight f2h -----------
// blocks [0,4096): transpose res -> AT hi/lo
// blocks [4096,5120): basis tables (cos/sin + DFT basis hi/lo)
// blocks [5120,7680): weight fp32->fp16
__global__ __launch_bounds__(256) void prep_kernel(const float* __restrict__ res,
                                                   const float4* __restrict__ Wi,
                                                   const float4* __restrict__ Wo,
                                                   const float4* __restrict__ W1,
                                                   const float4* __restrict__ W2) {
    int blk = blockIdx.x;
    int tid = threadIdx.x;
    if (blk < 4096) {
        __shared__ float tile[32][33];
        int b  = blk >> 8;
        int d0 = ((blk >> 4) & 15) * 32;
        int t0 = (blk & 15) * 32;
        int x = tid & 31, y = tid >> 5;
        const float* src = res + (size_t)b * 512 * 512;
        #pragma unroll
        for (int i = 0; i < 32; i += 8)
            tile[y + i][x] = src[(size_t)(t0 + y + i) * 512 + d0 + x];
        __syncthreads();
        #pragma unroll
        for (int i = 0; i < 32; i += 8) {
            float v = tile[x][y + i];
            __half hi = __float2half_rn(v);
            size_t idx = (size_t)(b*512 + d0 + y + i) * 512 + t0 + x;
            g_AThi[idx] = hi;
            g_ATlo[idx] = __float2half_rn(v - __half2float(hi));
        }
    } else if (blk < 5120) {
        int e = (blk - 4096) * 256 + tid;   // 0..262143
        int n = e >> 9;
        int t = e & 511;
        int k = n & 255;
        int m = (k * t) & 511;
        float ang = 6.283185307179586f * (float)m * (1.0f/512.0f);
        float s, c;
        sincosf(ang, &s, &c);
        if (n < 256) {
            g_cosT[n*512 + t] = c;
            g_sinT[n*512 + t] = s;
        }
        float val = (n < 256) ? c : -s;
        __half hi = __float2half_rn(val);
        g_Bhi[n*512 + t] = hi;
        g_Blo[n*512 + t] = __float2half_rn(val - __half2float(hi));
    } else {
        int i = (blk - 5120) * 256 + tid;   // 0..655359
        const float4* src; __half2* dst; int off;
        if (i < 65536)       { src = Wi; dst = (__half2*)g_Wih; off = i; }
        else if (i < 131072) { src = Wo; dst = (__half2*)g_Woh; off = i - 65536; }
        else if (i < 393216) { src = W1; dst = (__half2*)g_W1h; off = i - 131072; }
        else                 { src = W2; dst = (__half2*)g_W2h; off = i - 393216; }
        float4 v = src[off];
        __half2 h0 = __floats2half2_rn(v.x, v.y);
        __half2 h1 = __floats2half2_rn(v.z, v.w);
        uint2 pk = make_uint2(*(uint32_t*)&h0, *(uint32_t*)&h1);
        *(uint2*)(dst + 2*off) = pk;
    }
}

// -------- top-16 |X|^2 over k in [1,255]: sorted-lane tournament -----------
__global__ __launch_bounds__(256) void topk_kernel() {
    int warp = threadIdx.x >> 5, lane = threadIdx.x & 31;
    int bd = blockIdx.x * 8 + warp;
    const float* xr = g_X + (size_t)bd*512;
    const float* xi = xr + 256;

    unsigned long long key[8];
    #pragma unroll
    for (int j = 0; j < 8; j++) {
        int k = 1 + lane + 32*j;
        if (k <= 255) {
            float r = xr[k], q = xi[k];
            float m2 = fmaf(r, r, q*q);
            key[j] = ((unsigned long long)__float_as_uint(m2) << 32)
                   | (unsigned long long)(511 - k);
        } else key[j] = 0ull;
    }
    #define CSW(a_, b_) { unsigned long long hi_ = key[a_] > key[b_] ? key[a_] : key[b_]; \
                          unsigned long long lo_ = key[a_] > key[b_] ? key[b_] : key[a_]; \
                          key[a_] = hi_; key[b_] = lo_; }
    CSW(0,1) CSW(2,3) CSW(4,5) CSW(6,7)
    CSW(0,2) CSW(1,3) CSW(4,6) CSW(5,7)
    CSW(1,2) CSW(5,6)
    CSW(0,4) CSW(1,5) CSW(2,6) CSW(3,7)
    CSW(2,4) CSW(3,5)
    CSW(1,2) CSW(3,4) CSW(5,6)
    #undef CSW

    #pragma unroll 1
    for (int r = 0; r < 16; r++) {
        unsigned long long cur = key[0];
        unsigned long long m = cur;
        #pragma unroll
        for (int off = 16; off; off >>= 1) {
            unsigned long long o = __shfl_xor_sync(0xffffffffu, m, off);
            if (o > m) m = o;
        }
        if (cur == m) {
            #pragma unroll
            for (int i = 0; i < 7; i++) key[i] = key[i+1];
            key[7] = 0ull;
        }
        if (lane == 0) {
            int k = 511 - (int)(m & 0xffffffffull);
            g_kidx[r*NBD + bd] = k;
            g_ar[r*NBD + bd] = xr[k] * (2.0f/512.0f);
            g_ai[r*NBD + bd] = xi[k] * (2.0f/512.0f);
        }
    }
}

// ------- season synthesis (4-way rotation interleave) + res1h --------------
__global__ __launch_bounds__(256) void season_kernel(const float* __restrict__ res,
                                                     float* __restrict__ season) {
    int bd = blockIdx.x * 256 + threadIdx.x;
    int tt0 = blockIdx.y * 32;
    int b = bd >> 9, d = bd & 511;

    float acc[32];
    #pragma unroll
    for (int i = 0; i < 32; i++) acc[i] = 0.f;

    for (int j = 0; j < 16; j += 4) {
        float c[4], s[4], cd[4], sd[4], ar[4], ai[4];
        #pragma unroll
        for (int q = 0; q < 4; q++) {
            int   k = g_kidx[(j+q)*NBD + bd];
            ar[q] = g_ar[(j+q)*NBD + bd];
            ai[q] = g_ai[(j+q)*NBD + bd];
            int m = (k * tt0) & 511;
            c[q]  = g_cosT[512 + m];  s[q]  = g_sinT[512 + m];
            cd[q] = g_cosT[512 + k];  sd[q] = g_sinT[512 + k];
        }
        #pragma unroll
        for (int i = 0; i < 32; i++) {
            #pragma unroll
            for (int q = 0; q < 4; q++) {
                acc[i] = fmaf(ar[q], c[q], fmaf(-ai[q], s[q], acc[i]));
                float cn = fmaf(c[q], cd[q], -s[q]*sd[q]);
                s[q] = fmaf(s[q], cd[q], c[q]*sd[q]);
                c[q] = cn;
            }
        }
    }
    #pragma unroll
    for (int i = 0; i < 32; i++) {
        int tt = tt0 + i;
        float v = acc[i];
        season[((size_t)(b*608 + tt))*512 + d] = v;
        if (tt < 512) {
            size_t idx = ((size_t)(b*512 + tt))*512 + d;
            g_res1h[idx] = __float2half_rn(res[idx] - v);
        }
    }
}

// -------- growth EMA as 4-way affine scan (fp16 v input) -------------------
__global__ __launch_bounds__(256) void growth_ema_scan(const float* __restrict__ z0,
                                                       const float* __restrict__ v0g,
                                                       const float* __restrict__ sw_g) {
    int blk = blockIdx.x;
    int b   = blk >> 3;
    int hd0 = (blk & 7) << 6;
    int s   = threadIdx.x & 63;
    int q   = threadIdx.x >> 6;
    int hd  = hd0 + s;
    int h   = hd >> 6;
    float alpha = 1.f / (1.f + expf(-sw_g[h]));
    float oma = 1.f - alpha;
    float A = alpha;
    #pragma unroll
    for (int i = 0; i < 7; i++) A *= A;

    const __half* vcol = g_vh + (size_t)b*512*512 + hd;
    const int t0 = q << 7;

    float prev0 = (q == 0) ? z0[hd] : __half2float(vcol[(size_t)(t0 - 1)*512]);
    float prev = prev0;
    float S = 0.f;
    for (int j = 0; j < 128; j++) {
        float x = __half2float(vcol[(size_t)(t0 + j)*512]);
        S = fmaf(alpha, S, oma * (x - prev));
        prev = x;
    }
    __shared__ float Ss[4][64];
    Ss[q][s] = S;
    __syncthreads();

    float E = v0g[hd];
    for (int p = 0; p < q; p++) E = fmaf(A, E, Ss[p][s]);

    prev = prev0;
    float st = E;
    __half* go = g_gr + ((size_t)(b*513 + 1 + t0))*512 + hd;
    if (q == 0) g_gr[((size_t)(b*513))*512 + hd] = __float2half_rn(E);
    for (int j = 0; j < 128; j++) {
        float x = __half2float(vcol[(size_t)(t0 + j)*512]);
        st = fmaf(alpha, st, oma * (x - prev));
        prev = x;
        go[(size_t)j*512] = __float2half_rn(st);
    }
}

// -------- LN helpers --------
__global__ __launch_bounds__(256) void ln_sub_kernel(const float* __restrict__ growth,
                                                     const float* __restrict__ g,
                                                     const float* __restrict__ be) {
    int row = blockIdx.x;
    int b = row >> 9, t = row & 511;
    const __half* pa = g_res1h + (size_t)row*512;
    const float*  pb = growth + (size_t)(b*513 + t + 1)*512;
    int tid = threadIdx.x;
    float x0 = __half2float(pa[tid])       - pb[tid];
    float x1 = __half2float(pa[tid + 256]) - pb[tid + 256];
    __shared__ float red[18];
    float s = x0 + x1, q = fmaf(x0, x0, x1*x1);
    int lane = tid & 31, warp = tid >> 5;
    #pragma unroll
    for (int o = 16; o; o >>= 1) { s += __shfl_xor_sync(~0u, s, o); q += __shfl_xor_sync(~0u, q, o); }
    if (lane == 0) { red[warp] = s; red[8 + warp] = q; }
    __syncthreads();
    if (tid < 32) {
        s = (tid < 8) ? red[tid] : 0.f;
        q = (tid < 8) ? red[8 + tid] : 0.f;
        #pragma unroll
        for (int o = 4; o; o >>= 1) { s += __shfl_xor_sync(~0u, s, o); q += __shfl_xor_sync(~0u, q, o); }
        if (tid == 0) {
            float mu = s * (1.f/512.f);
            float var = q * (1.f/512.f) - mu*mu;
            red[16] = mu; red[17] = rsqrtf(var + 1e-5f);
        }
    }
    __syncthreads();
    float mu = red[16], r = red[17];
    float h0  = (x0 - mu)*r*g[tid]       + be[tid];
    float h1v = (x1 - mu)*r*g[tid + 256] + be[tid + 256];
    g_h1h[(size_t)row*512 + tid]       = __float2half_rn(h0);
    g_h1h[(size_t)row*512 + tid + 256] = __float2half_rn(h1v);
}

__global__ __launch_bounds__(256) void ln_add_kernel(const float* __restrict__ g,
                                                     const float* __restrict__ be,
                                                     float* __restrict__ out) {
    int row = blockIdx.x;
    const __half* pa = g_h1h  + (size_t)row*512;
    const __half* pb = g_ff2h + (size_t)row*512;
    int tid = threadIdx.x;
    float x0 = __half2float(pa[tid])       + __half2float(pb[tid]);
    float x1 = __half2float(pa[tid + 256]) + __half2float(pb[tid + 256]);
    __shared__ float red[18];
    float s = x0 + x1, q = fmaf(x0, x0, x1*x1);
    int lane = tid & 31, warp = tid >> 5;
    #pragma unroll
    for (int o = 16; o; o >>= 1) { s += __shfl_xor_sync(~0u, s, o); q += __shfl_xor_sync(~0u, q, o); }
    if (lane == 0) { red[warp] = s; red[8 + warp] = q; }
    __syncthreads();
    if (tid < 32) {
        s = (tid < 8) ? red[tid] : 0.f;
        q = (tid < 8) ? red[8 + tid] : 0.f;
        #pragma unroll
        for (int o = 4; o; o >>= 1) { s += __shfl_xor_sync(~0u, s, o); q += __shfl_xor_sync(~0u, q, o); }
        if (tid == 0) {
            float mu = s * (1.f/512.f);
            float var = q * (1.f/512.f) - mu*mu;
            red[16] = mu; red[17] = rsqrtf(var + 1e-5f);
        }
    }
    __syncthreads();
    float mu = red[16], r = red[17];
    float* po = out + (size_t)row*512;
    po[tid]       = (x0 - mu)*r*g[tid]       + be[tid];
    po[tid + 256] = (x1 - mu)*r*g[tid + 256] + be[tid + 256];
}

// -------- gp/sp projections, 4 rows per block ------------------------------
__global__ __launch_bounds__(256) void proj7_kernel(const float* __restrict__ growth,
                                                    const float* __restrict__ season,
                                                    const float* __restrict__ Wg,
                                                    const float* __restrict__ bg,
                                                    const float* __restrict__ Ws,
                                                    const float* __restrict__ bs) {
    int row0 = blockIdx.x * 4;
    int tid = threadIdx.x;
    __shared__ float gx[4][512], sx[4][512];
    #pragma unroll
    for (int rr = 0; rr < 4; rr++) {
        int row = row0 + rr;
        int b = row >> 9, t = row & 511;
        const float* grow = growth + (size_t)(b*513 + t + 1)*512;
        const float* srow = season + (size_t)(b*608 + t)*512;
        for (int i = tid; i < 512; i += 256) { gx[rr][i] = grow[i]; sx[rr][i] = srow[i]; }
    }
    __syncthreads();
    int warp = tid >> 5, lane = tid & 31;
    for (int task = warp; task < 28; task += 8) {
        int rr = task / 7, c = task - rr*7;
        float s1 = 0.f, s2 = 0.f;
        const float* wg = Wg + c*512;
        const float* ws = Ws + c*512;
        for (int i = lane; i < 512; i += 32) {
            s1 = fmaf(gx[rr][i], wg[i], s1);
            s2 = fmaf(sx[rr][i], ws[i], s2);
        }
        #pragma unroll
        for (int o = 16; o; o >>= 1) {
            s1 += __shfl_xor_sync(~0u, s1, o);
            s2 += __shfl_xor_sync(~0u, s2, o);
        }
        if (lane == 0) {
            int row = row0 + rr;
            g_gp[row*7 + c] = s1 + bg[c];
            g_sp[row*7 + c] = s2 + bs[c];
        }
    }
}

// -------- level EMA with aux: warp-parallel affine scan --------
__global__ __launch_bounds__(256) void level_scan_kernel(const float* __restrict__ level,
                                                         const float* __restrict__ sw_l,
                                                         const float* __restrict__ v0_l,
                                                         float* __restrict__ lvl_out) {
    int w = (blockIdx.x * blockDim.x + threadIdx.x) >> 5;
    int lane = threadIdx.x & 31;
    if (w >= BB * COUTN) return;
    int b = w / COUTN, c = w % COUTN;
    float alpha = 1.f / (1.f + expf(-sw_l[c]));
    float oma = 1.f - alpha;
    float a2 = alpha*alpha, a4 = a2*a2, a8 = a4*a4;
    float P16 = a8*a8;

    int base = (b*512 + lane*16)*COUTN + c;
    float u1[16], u2[16];
    #pragma unroll
    for (int j = 0; j < 16; j++) {
        int idx = base + j*COUTN;
        u1[j] = oma * (level[idx] - g_sp[idx]);
        u2[j] = alpha * g_gp[idx];
    }
    float S1 = 0.f, S2 = 0.f;
    #pragma unroll
    for (int j = 0; j < 16; j++) { S1 = fmaf(alpha, S1, u1[j]); S2 = fmaf(alpha, S2, u2[j]); }
    float P = P16;
    #pragma unroll
    for (int d = 1; d < 32; d <<= 1) {
        float Pp  = __shfl_up_sync(~0u, P,  d);
        float S1p = __shfl_up_sync(~0u, S1, d);
        float S2p = __shfl_up_sync(~0u, S2, d);
        if (lane >= d) { S1 = fmaf(P, S1p, S1); S2 = fmaf(P, S2p, S2); P *= Pp; }
    }
    float Px  = __shfl_up_sync(~0u, P,  1);
    float S1x = __shfl_up_sync(~0u, S1, 1);
    float S2x = __shfl_up_sync(~0u, S2, 1);
    if (lane == 0) { Px = 1.f; S1x = 0.f; S2x = 0.f; }
    float s   = fmaf(Px, v0_l[c], S1x);
    float aux = S2x;
    #pragma unroll
    for (int j = 0; j < 16; j++) {
        s   = fmaf(alpha, s,   u1[j]);
        aux = fmaf(alpha, aux, u2[j]);
        lvl_out[base + j*COUTN] = s + aux;
    }
}

// ---------------- launch ----------------
extern "C" void kernel_launch(void* const* d_in, const int* in_sizes, int n_in,
                              void* d_out, int out_size) {
    const float* res   = (const float*)d_in[0];
    const float* level = (const float*)d_in[1];
    const float* Wi    = (const float*)d_in[2];
    const float* bi    = (const float*)d_in[3];
    const float* z0    = (const float*)d_in[4];
    const float* v0_g  = (const float*)d_in[5];
    const float* sw_g  = (const float*)d_in[6];
    const float* Wo    = (const float*)d_in[7];
    const float* bo    = (const float*)d_in[8];
    const float* W1    = (const float*)d_in[9];
    const float* W2    = (const float*)d_in[10];
    const float* g1    = (const float*)d_in[11];
    const float* b1    = (const float*)d_in[12];
    const float* g2    = (const float*)d_in[13];
    const float* b2    = (const float*)d_in[14];
    const float* Wg    = (const float*)d_in[15];
    const float* bg    = (const float*)d_in[16];
    const float* Ws    = (const float*)d_in[17];
    const float* bs    = (const float*)d_in[18];
    const float* v0_l  = (const float*)d_in[19];
    const float* sw_l  = (const float*)d_in[20];
    float* out = (float*)d_out;

    __half *p_res1h, *p_vh, *p_gr, *p_h1h, *p_ffb, *p_ff2h, *p_Wih, *p_Woh, *p_W1h, *p_W2h;
    cudaGetSymbolAddress((void**)&p_res1h, g_res1h);
    cudaGetSymbolAddress((void**)&p_vh,    g_vh);
    cudaGetSymbolAddress((void**)&p_gr,    g_gr);
    cudaGetSymbolAddress((void**)&p_h1h,   g_h1h);
    cudaGetSymbolAddress((void**)&p_ffb,   g_ffb);
    cudaGetSymbolAddress((void**)&p_ff2h,  g_ff2h);
    cudaGetSymbolAddress((void**)&p_Wih,   g_Wih);
    cudaGetSymbolAddress((void**)&p_Woh,   g_Woh);
    cudaGetSymbolAddress((void**)&p_W1h,   g_W1h);
    cudaGetSymbolAddress((void**)&p_W2h,   g_W2h);

    cudaFuncSetAttribute(hgemm<false,true,true>,  cudaFuncAttributeMaxDynamicSharedMemorySize, G_SMEM_DYN);
    cudaFuncSetAttribute(hgemm<false,true,false>, cudaFuncAttributeMaxDynamicSharedMemorySize, G_SMEM_DYN);
    cudaFuncSetAttribute(hgemm<true,false,true>,  cudaFuncAttributeMaxDynamicSharedMemorySize, G_SMEM_DYN);
    cudaFuncSetAttribute(hgemm<false,false,true>, cudaFuncAttributeMaxDynamicSharedMemorySize, G_SMEM_DYN);
    cudaFuncSetAttribute(dft_split_hgemm,         cudaFuncAttributeMaxDynamicSharedMemorySize, DFT_SMEM_DYN);

    float* out_season = out + OFF_SEASON;
    float* out_growth = out + OFF_GROWTH;
    float* out_lvl    = out + OFF_LVL;

    // 1. fused prep (transpose/split + basis + weight f2h)
    prep_kernel<<<7680, 256>>>(res, (const float4*)Wi, (const float4*)Wo,
                               (const float4*)W1, (const float4*)W2);
    // 2. DFT on tensor cores (split-fp16, R8 config)
    dft_split_hgemm<<<dim3(4, 64), 256, DFT_SMEM_DYN>>>();
    // 3. top-16 per (b,d)
    topk_kernel<<<NBD/8, 256>>>();
    // 4. season + res1h
    season_kernel<<<dim3(32, 19), 256>>>(res, out_season);
    // 5. v = res1 @ Wi^T + bi  -> fp16
    hgemm<false,true,true><<<dim3(4, 64), 256, G_SMEM_DYN>>>(p_res1h, p_Wih, bi, nullptr, p_vh, NROW, 512, 512);
    // 6. growth EMA scan (fp16 v)
    growth_ema_scan<<<128, 256>>>(z0, v0_g, sw_g);
    // 7. growth = gr @ Wo^T + bo -> d_out (fp32)
    hgemm<false,true,false><<<dim3(4, 65), 256, G_SMEM_DYN>>>(p_gr, p_Woh, bo, out_growth, nullptr, NROWG, 512, 512);
    // 8. h1 = LN(res1 - growth[:,1:]) -> fp16
    ln_sub_kernel<<<NROW, 256>>>(out_growth, g1, b1);
    // 9. ffb = relu(h1 @ W1^T) -> fp16
    hgemm<true,false,true><<<dim3(16, 64), 256, G_SMEM_DYN>>>(p_h1h, p_W1h, nullptr, nullptr, p_ffb, NROW, DFFN, 512);
    // 10. ff2 = ffb @ W2^T -> fp16
    hgemm<false,false,true><<<dim3(4, 64), 256, G_SMEM_DYN>>>(p_ffb, p_W2h, nullptr, nullptr, p_ff2h, NROW, 512, DFFN);
    // 11. h = LN(h1 + ff2) -> d_out
    ln_add_kernel<<<NROW, 256>>>(g2, b2, out + OFF_H);
    // 12. gp/sp projections (4 rows/block)
    proj7_kernel<<<NROW/4, 256>>>(out_growth, out_season, Wg, bg, Ws, bs);
    // 13. level EMA (warp affine scan) -> d_out
    level_scan_kernel<<<(BB*COUTN*32 + 255)/256, 256>>>(level, sw_l, v0_l, out_lvl);
}

// round 15
// speedup vs baseline: 1.0015x; 1.0011x over previous
#include <cuda_runtime.h>
#include <cuda_fp16.h>
#include <math.h>
#include <cstdint>

// ---------------- problem constants ----------------
#define BB    16
#define TT_   512
#define DD    512
#define COUTN 7
#define DFFN  2048
#define NROW  (BB*TT_)     // 8192
#define NROWG (BB*513)     // 8208
#define NBD   (BB*DD)      // 8192 series for fourier

// output tuple layout: (h, lvl, growth, season) flattened fp32
#define OFF_H      0
#define OFF_LVL    ((size_t)BB*TT_*DD)                 // 4194304
#define OFF_GROWTH (OFF_LVL + (size_t)BB*TT_*COUTN)    // 4251648
#define OFF_SEASON (OFF_GROWTH + (size_t)BB*513*DD)    // 8454144

// ---------------- scratch (__device__ globals; no allocs) ----------------
__device__ float  g_cosT [256*512];
__device__ float  g_sinT [256*512];
__device__ __half g_Bhi[512*512];
__device__ __half g_Blo[512*512];
__device__ __half g_AThi[(size_t)NBD*512];
__device__ __half g_ATlo[(size_t)NBD*512];
__device__ float  g_X[(size_t)NBD*512];      // [bd][0:256)=re, [256:512)=im
__device__ int    g_kidx[16*NBD];
__device__ float  g_ar[16*NBD];
__device__ float  g_ai[16*NBD];
__device__ __half g_res1h[(size_t)NROW*DD];
__device__ __half g_vh[(size_t)NROW*DD];
__device__ __half g_gr[(size_t)NROWG*DD];
__device__ __half g_h1h[(size_t)NROW*DD];
__device__ __half g_ffb[(size_t)NROW*DFFN];
__device__ __half g_ff2h[(size_t)NROW*DD];
__device__ float  g_gp[NROW*COUTN];
__device__ float  g_sp[NROW*COUTN];
// fp16 weights
__device__ __half g_Wih[512*512];
__device__ __half g_Woh[512*512];
__device__ __half g_W1h[2048*512];
__device__ __half g_W2h[512*2048];

// ---------------- common helpers ----------------
__device__ __forceinline__ uint32_t smem_u32(const void* p) {
    uint32_t a;
    asm("{ .reg .u64 t; cvta.to.shared.u64 t, %1; cvt.u32.u64 %0, t; }" : "=r"(a) : "l"(p));
    return a;
}
__device__ __forceinline__ void cp16(uint32_t dst, const void* src) {
    asm volatile("cp.async.cg.shared.global [%0], [%1], 16;"
                 :: "r"(dst), "l"(__cvta_generic_to_global(src)) : "memory");
}
#define CP_COMMIT() asm volatile("cp.async.commit_group;" ::: "memory")
#define CP_WAIT1()  asm volatile("cp.async.wait_group 1;" ::: "memory")

#define LDSM_X4(r0, r1, r2, r3, addr) \
    asm volatile("ldmatrix.sync.aligned.m8n8.x4.shared.b16 {%0,%1,%2,%3}, [%4];" \
        : "=r"(r0), "=r"(r1), "=r"(r2), "=r"(r3) : "r"(addr))

#define MMA_F16(c, a, b) \
    asm volatile("mma.sync.aligned.m16n8k16.row.col.f32.f16.f16.f32 " \
        "{%0,%1,%2,%3}, {%4,%5,%6,%7}, {%8,%9}, {%0,%1,%2,%3};" \
        : "+f"((c)[0]), "+f"((c)[1]), "+f"((c)[2]), "+f"((c)[3]) \
        : "r"((a)[0]), "r"((a)[1]), "r"((a)[2]), "r"((a)[3]), \
          "r"((b)[0]), "r"((b)[1]))

// ============== fp16 HMMA GEMM: C[M,N] = A[M,K] @ W[N,K]^T =============
// block 128x128, K-chunk 64 halves, 8 warps (2x4), cp.async 3-stage, 2 CTA/SM.
#define G_SMEM_DYN (3*32768)

template<bool RELU, bool BIAS, bool HALF_OUT>
__global__ __launch_bounds__(256, 2)
void hgemm(const __half* __restrict__ A, const __half* __restrict__ W,
           const float* __restrict__ bias, float* __restrict__ C,
           __half* __restrict__ Ch, int M, int N, int K)
{
    extern __shared__ char smraw[];
    const uint32_t smem = smem_u32(smraw);
    const int tid  = threadIdx.x;
    const int bm   = blockIdx.y * 128;
    const int bn   = blockIdx.x * 128;
    const int lane = tid & 31;
    const int w    = tid >> 5;
    const int m_base = (w >> 2) * 64;
    const int n_base = (w & 3) * 32;

    int str[4], stg[4];
    #pragma unroll
    for (int i = 0; i < 4; i++) {
        int gid = tid + 256 * i;
        str[i] = gid >> 3;
        stg[i] = gid & 7;
    }

    const int rowA  = m_base + (lane & 15);
    const uint32_t cxA = (uint32_t)(rowA & 7);
    const uint32_t gA  = (uint32_t)(lane >> 4);
    uint32_t rowOffA[4];
    #pragma unroll
    for (int mi = 0; mi < 4; mi++) rowOffA[mi] = (uint32_t)(rowA + mi*16) << 7;

    const uint32_t cxB = (uint32_t)(lane & 7);
    const uint32_t gB  = (uint32_t)((lane >> 3) & 1);
    uint32_t rowOffB[2];
    #pragma unroll
    for (int p = 0; p < 2; p++) {
        int rowB = n_base + p*16 + (lane & 7) + ((lane >> 4) << 3);
        rowOffB[p] = (uint32_t)rowB << 7;
    }

    float acc[4][4][4];
    #pragma unroll
    for (int mi = 0; mi < 4; mi++)
        #pragma unroll
        for (int nj = 0; nj < 4; nj++)
            #pragma unroll
            for (int e = 0; e < 4; e++) acc[mi][nj][e] = 0.f;

    const int nch = K >> 6;

    auto issue = [&](int c) {
        const int k0 = c << 6;
        const uint32_t st  = smem + (uint32_t)(c % 3) * 32768;
        const uint32_t stB = st + 16384;
        #pragma unroll
        for (int i = 0; i < 4; i++) {
            uint32_t off = ((uint32_t)str[i] << 7) + (uint32_t)((stg[i] ^ (str[i] & 7)) << 4);
            int rm = bm + str[i]; if (rm > M - 1) rm = M - 1;
            cp16(st  + off, A + (size_t)rm * K + k0 + stg[i]*8);
            cp16(stB + off, W + (size_t)(bn + str[i]) * K + k0 + stg[i]*8);
        }
        CP_COMMIT();
    };
    auto compute_chunk = [&](int s) {
        const uint32_t stA = smem + (uint32_t)s * 32768;
        const uint32_t stB = stA + 16384;
        #pragma unroll
        for (int k16 = 0; k16 < 4; k16++) {
            uint32_t a[4][4];
            #pragma unroll
            for (int mi = 0; mi < 4; mi++) {
                uint32_t ad = stA + rowOffA[mi] + ((((uint32_t)(k16*2) + gA) ^ cxA) << 4);
                LDSM_X4(a[mi][0], a[mi][1], a[mi][2], a[mi][3], ad);
            }
            uint32_t b[4][2];
            #pragma unroll
            for (int p = 0; p < 2; p++) {
                uint32_t bd = stB + rowOffB[p] + ((((uint32_t)(k16*2) + gB) ^ cxB) << 4);
                LDSM_X4(b[2*p][0], b[2*p][1], b[2*p+1][0], b[2*p+1][1], bd);
            }
            #pragma unroll
            for (int mi = 0; mi < 4; mi++)
                #pragma unroll
                for (int nj = 0; nj < 4; nj++)
                    MMA_F16(acc[mi][nj], a[mi], b[nj]);
        }
    };

    issue(0);
    if (nch > 1) issue(1);

    for (int c = 0; c < nch; c++) {
        CP_WAIT1();
        __syncthreads();
        if (c + 2 < nch) issue(c + 2);
        compute_chunk(c % 3);
    }

    #pragma unroll
    for (int mi = 0; mi < 4; mi++) {
        const int r0 = bm + m_base + mi*16 + (lane >> 2);
        const int r1 = r0 + 8;
        #pragma unroll
        for (int nj = 0; nj < 4; nj++) {
            const int col = bn + n_base + nj*8 + (lane & 3)*2;
            float2 v0 = make_float2(acc[mi][nj][0], acc[mi][nj][1]);
            float2 v1 = make_float2(acc[mi][nj][2], acc[mi][nj][3]);
            if (BIAS) {
                float bx = bias[col], by = bias[col + 1];
                v0.x += bx; v0.y += by; v1.x += bx; v1.y += by;
            }
            if (RELU) {
                v0.x = fmaxf(v0.x, 0.f); v0.y = fmaxf(v0.y, 0.f);
                v1.x = fmaxf(v1.x, 0.f); v1.y = fmaxf(v1.y, 0.f);
            }
            if (HALF_OUT) {
                if (r0 < M) *(__half2*)(Ch + (size_t)r0 * N + col) = __floats2half2_rn(v0.x, v0.y);
                if (r1 < M) *(__half2*)(Ch + (size_t)r1 * N + col) = __floats2half2_rn(v1.x, v1.y);
            } else {
                if (r0 < M) *(float2*)(C + (size_t)r0 * N + col) = v0;
                if (r1 < M) *(float2*)(C + (size_t)r1 * N + col) = v1;
            }
        }
    }
}

// ====== split-fp16 DFT GEMM (R8 config): X = AT @ B^T, 64KB stages =========
#define DFT_SMEM_DYN (3*65536)

__global__ __launch_bounds__(256)
void dft_split_hgemm()
{
    extern __shared__ char smraw[];
    const uint32_t smem = smem_u32(smraw);
    const __half* __restrict__ Ahi = g_AThi;
    const __half* __restrict__ Alo = g_ATlo;
    const __half* __restrict__ Bhi = g_Bhi;
    const __half* __restrict__ Blo = g_Blo;
    const int tid  = threadIdx.x;
    const int bm   = blockIdx.y * 128;
    const int bn   = blockIdx.x * 128;
    const int lane = tid & 31;
    const int w    = tid >> 5;
    const int m_base = (w >> 2) * 64;
    const int n_base = (w & 3) * 32;

    int str[4], stg[4];
    #pragma unroll
    for (int i = 0; i < 4; i++) {
        int gid = tid + 256 * i;
        str[i] = gid >> 3;
        stg[i] = gid & 7;
    }

    const int rowA  = m_base + (lane & 15);
    const uint32_t cxA = (uint32_t)(rowA & 7);
    const uint32_t gA  = (uint32_t)(lane >> 4);
    uint32_t rowOffA[4];
    #pragma unroll
    for (int mi = 0; mi < 4; mi++) rowOffA[mi] = (uint32_t)(rowA + mi*16) << 7;

    const uint32_t cxB = (uint32_t)(lane & 7);
    const uint32_t gB  = (uint32_t)((lane >> 3) & 1);
    uint32_t rowOffB[2];
    #pragma unroll
    for (int p = 0; p < 2; p++) {
        int rowB = n_base + p*16 + (lane & 7) + ((lane >> 4) << 3);
        rowOffB[p] = (uint32_t)rowB << 7;
    }

    float acc[4][4][4];
    #pragma unroll
    for (int mi = 0; mi < 4; mi++)
        #pragma unroll
        for (int nj = 0; nj < 4; nj++)
            #pragma unroll
            for (int e = 0; e < 4; e++) acc[mi][nj][e] = 0.f;

    const int nch = 8;

    auto issue = [&](int c) {
        const int k0 = c << 6;
        const uint32_t st = smem + (uint32_t)(c % 3) * 65536;
        #pragma unroll
        for (int i = 0; i < 4; i++) {
            uint32_t off = ((uint32_t)str[i] << 7) + (uint32_t)((stg[i] ^ (str[i] & 7)) << 4);
            size_t offA = (size_t)(bm + str[i]) * 512 + k0 + stg[i]*8;
            size_t offB = (size_t)(bn + str[i]) * 512 + k0 + stg[i]*8;
            cp16(st + off,         Ahi + offA);
            cp16(st + 16384 + off, Alo + offA);
            cp16(st + 32768 + off, Bhi + offB);
            cp16(st + 49152 + off, Blo + offB);
        }
        CP_COMMIT();
    };
    auto compute_chunk = [&](int s) {
        const uint32_t st = smem + (uint32_t)s * 65536;
        #pragma unroll
        for (int k16 = 0; k16 < 4; k16++) {
            uint32_t aH[4][4], aL[4][4];
            #pragma unroll
            for (int mi = 0; mi < 4; mi++) {
                uint32_t xo = rowOffA[mi] + ((((uint32_t)(k16*2) + gA) ^ cxA) << 4);
                LDSM_X4(aH[mi][0], aH[mi][1], aH[mi][2], aH[mi][3], st + xo);
                LDSM_X4(aL[mi][0], aL[mi][1], aL[mi][2], aL[mi][3], st + 16384 + xo);
            }
            uint32_t bH[4][2], bL[4][2];
            #pragma unroll
            for (int p = 0; p < 2; p++) {
                uint32_t xo = rowOffB[p] + ((((uint32_t)(k16*2) + gB) ^ cxB) << 4);
                LDSM_X4(bH[2*p][0], bH[2*p][1], bH[2*p+1][0], bH[2*p+1][1], st + 32768 + xo);
                LDSM_X4(bL[2*p][0], bL[2*p][1], bL[2*p+1][0], bL[2*p+1][1], st + 49152 + xo);
            }
            #pragma unroll
            for (int mi = 0; mi < 4; mi++)
                #pragma unroll
                for (int nj = 0; nj < 4; nj++) {
                    MMA_F16(acc[mi][nj], aL[mi], bH[nj]);
                    MMA_F16(acc[mi][nj], aH[mi], bL[nj]);
                    MMA_F16(acc[mi][nj], aH[mi], bH[nj]);
                }
        }
    };

    issue(0);
    issue(1);

    for (int c = 0; c < nch; c++) {
        CP_WAIT1();
        __syncthreads();
        if (c + 2 < nch) issue(c + 2);
        compute_chunk(c % 3);
    }

    #pragma unroll
    for (int mi = 0; mi < 4; mi++) {
        const int r0 = bm + m_base + mi*16 + (lane >> 2);
        const int r1 = r0 + 8;
        #pragma unroll
        for (int nj = 0; nj < 4; nj++) {
            const int col = bn + n_base + nj*8 + (lane & 3)*2;
            *(float2*)(g_X + (size_t)r0 * 512 + col) = make_float2(acc[mi][nj][0], acc[mi][nj][1]);
            *(float2*)(g_X + (size_t)r1 * 512 + col) = make_float2(acc[mi][nj][2], acc[mi][nj][3]);
        }
    }
}

// ------- fused prep: transpose/split + basis tables + weight f2h -----------
// blocks [0,4096): transpose res -> AT hi/lo
// blocks [4096,5120): basis tables (cos/sin + DFT basis hi/lo)
// blocks [5120,7680): weight fp32->fp16
__global__ __launch_bounds__(256) void prep_kernel(const float* __restrict__ res,
                                                   const float4* __restrict__ Wi,
                                                   const float4* __restrict__ Wo,
                                                   const float4* __restrict__ W1,
                                                   const float4* __restrict__ W2) {
    int blk = blockIdx.x;
    int tid = threadIdx.x;
    if (blk < 4096) {
        __shared__ float tile[32][33];
        int b  = blk >> 8;
        int d0 = ((blk >> 4) & 15) * 32;
        int t0 = (blk & 15) * 32;
        int x = tid & 31, y = tid >> 5;
        const float* src = res + (size_t)b * 512 * 512;
        #pragma unroll
        for (int i = 0; i < 32; i += 8)
            tile[y + i][x] = src[(size_t)(t0 + y + i) * 512 + d0 + x];
        __syncthreads();
        #pragma unroll
        for (int i = 0; i < 32; i += 8) {
            float v = tile[x][y + i];
            __half hi = __float2half_rn(v);
            size_t idx = (size_t)(b*512 + d0 + y + i) * 512 + t0 + x;
            g_AThi[idx] = hi;
            g_ATlo[idx] = __float2half_rn(v - __half2float(hi));
        }
    } else if (blk < 5120) {
        int e = (blk - 4096) * 256 + tid;   // 0..262143
        int n = e >> 9;
        int t = e & 511;
        int k = n & 255;
        int m = (k * t) & 511;
        float ang = 6.283185307179586f * (float)m * (1.0f/512.0f);
        float s, c;
        sincosf(ang, &s, &c);
        if (n < 256) {
            g_cosT[n*512 + t] = c;
            g_sinT[n*512 + t] = s;
        }
        float val = (n < 256) ? c : -s;
        __half hi = __float2half_rn(val);
        g_Bhi[n*512 + t] = hi;
        g_Blo[n*512 + t] = __float2half_rn(val - __half2float(hi));
    } else {
        int i = (blk - 5120) * 256 + tid;   // 0..655359
        const float4* src; __half2* dst; int off;
        if (i < 65536)       { src = Wi; dst = (__half2*)g_Wih; off = i; }
        else if (i < 131072) { src = Wo; dst = (__half2*)g_Woh; off = i - 65536; }
        else if (i < 393216) { src = W1; dst = (__half2*)g_W1h; off = i - 131072; }
        else                 { src = W2; dst = (__half2*)g_W2h; off = i - 393216; }
        float4 v = src[off];
        __half2 h0 = __floats2half2_rn(v.x, v.y);
        __half2 h1 = __floats2half2_rn(v.z, v.w);
        uint2 pk = make_uint2(*(uint32_t*)&h0, *(uint32_t*)&h1);
        *(uint2*)(dst + 2*off) = pk;
    }
}

// -------- top-16 |X|^2 over k in [1,255]: sorted-lane tournament -----------
__global__ __launch_bounds__(256) void topk_kernel() {
    int warp = threadIdx.x >> 5, lane = threadIdx.x & 31;
    int bd = blockIdx.x * 8 + warp;
    const float* xr = g_X + (size_t)bd*512;
    const float* xi = xr + 256;

    unsigned long long key[8];
    #pragma unroll
    for (int j = 0; j < 8; j++) {
        int k = 1 + lane + 32*j;
        if (k <= 255) {
            float r = xr[k], q = xi[k];
            float m2 = fmaf(r, r, q*q);
            key[j] = ((unsigned long long)__float_as_uint(m2) << 32)
                   | (unsigned long long)(511 - k);
        } else key[j] = 0ull;
    }
    #define CSW(a_, b_) { unsigned long long hi_ = key[a_] > key[b_] ? key[a_] : key[b_]; \
                          unsigned long long lo_ = key[a_] > key[b_] ? key[b_] : key[a_]; \
                          key[a_] = hi_; key[b_] = lo_; }
    CSW(0,1) CSW(2,3) CSW(4,5) CSW(6,7)
    CSW(0,2) CSW(1,3) CSW(4,6) CSW(5,7)
    CSW(1,2) CSW(5,6)
    CSW(0,4) CSW(1,5) CSW(2,6) CSW(3,7)
    CSW(2,4) CSW(3,5)
    CSW(1,2) CSW(3,4) CSW(5,6)
    #undef CSW

    #pragma unroll 1
    for (int r = 0; r < 16; r++) {
        unsigned long long cur = key[0];
        unsigned long long m = cur;
        #pragma unroll
        for (int off = 16; off; off >>= 1) {
            unsigned long long o = __shfl_xor_sync(0xffffffffu, m, off);
            if (o > m) m = o;
        }
        if (cur == m) {
            #pragma unroll
            for (int i = 0; i < 7; i++) key[i] = key[i+1];
            key[7] = 0ull;
        }
        if (lane == 0) {
            int k = 511 - (int)(m & 0xffffffffull);
            g_kidx[r*NBD + bd] = k;
            g_ar[r*NBD + bd] = xr[k] * (2.0f/512.0f);
            g_ai[r*NBD + bd] = xi[k] * (2.0f/512.0f);
        }
    }
}

// ------- season synthesis (4-way rotation interleave) + res1h --------------
__global__ __launch_bounds__(256) void season_kernel(const float* __restrict__ res,
                                                     float* __restrict__ season) {
    int bd = blockIdx.x * 256 + threadIdx.x;
    int tt0 = blockIdx.y * 32;
    int b = bd >> 9, d = bd & 511;

    float acc[32];
    #pragma unroll
    for (int i = 0; i < 32; i++) acc[i] = 0.f;

    for (int j = 0; j < 16; j += 4) {
        float c[4], s[4], cd[4], sd[4], ar[4], ai[4];
        #pragma unroll
        for (int q = 0; q < 4; q++) {
            int   k = g_kidx[(j+q)*NBD + bd];
            ar[q] = g_ar[(j+q)*NBD + bd];
            ai[q] = g_ai[(j+q)*NBD + bd];
            int m = (k * tt0) & 511;
            c[q]  = g_cosT[512 + m];  s[q]  = g_sinT[512 + m];
            cd[q] = g_cosT[512 + k];  sd[q] = g_sinT[512 + k];
        }
        #pragma unroll
        for (int i = 0; i < 32; i++) {
            #pragma unroll
            for (int q = 0; q < 4; q++) {
                acc[i] = fmaf(ar[q], c[q], fmaf(-ai[q], s[q], acc[i]));
                float cn = fmaf(c[q], cd[q], -s[q]*sd[q]);
                s[q] = fmaf(s[q], cd[q], c[q]*sd[q]);
                c[q] = cn;
            }
        }
    }
    #pragma unroll
    for (int i = 0; i < 32; i++) {
        int tt = tt0 + i;
        float v = acc[i];
        season[((size_t)(b*608 + tt))*512 + d] = v;
        if (tt < 512) {
            size_t idx = ((size_t)(b*512 + tt))*512 + d;
            g_res1h[idx] = __float2half_rn(res[idx] - v);
        }
    }
}

// -------- growth EMA as 4-way affine scan (fp16 v input) -------------------
__global__ __launch_bounds__(256) void growth_ema_scan(const float* __restrict__ z0,
                                                       const float* __restrict__ v0g,
                                                       const float* __restrict__ sw_g) {
    int blk = blockIdx.x;
    int b   = blk >> 3;
    int hd0 = (blk & 7) << 6;
    int s   = threadIdx.x & 63;
    int q   = threadIdx.x >> 6;
    int hd  = hd0 + s;
    int h   = hd >> 6;
    float alpha = 1.f / (1.f + expf(-sw_g[h]));
    float oma = 1.f - alpha;
    float A = alpha;
    #pragma unroll
    for (int i = 0; i < 7; i++) A *= A;

    const __half* vcol = g_vh + (size_t)b*512*512 + hd;
    const int t0 = q << 7;

    float prev0 = (q == 0) ? z0[hd] : __half2float(vcol[(size_t)(t0 - 1)*512]);
    float prev = prev0;
    float S = 0.f;
    for (int j = 0; j < 128; j++) {
        float x = __half2float(vcol[(size_t)(t0 + j)*512]);
        S = fmaf(alpha, S, oma * (x - prev));
        prev = x;
    }
    __shared__ float Ss[4][64];
    Ss[q][s] = S;
    __syncthreads();

    float E = v0g[hd];
    for (int p = 0; p < q; p++) E = fmaf(A, E, Ss[p][s]);

    prev = prev0;
    float st = E;
    __half* go = g_gr + ((size_t)(b*513 + 1 + t0))*512 + hd;
    if (q == 0) g_gr[((size_t)(b*513))*512 + hd] = __float2half_rn(E);
    for (int j = 0; j < 128; j++) {
        float x = __half2float(vcol[(size_t)(t0 + j)*512]);
        st = fmaf(alpha, st, oma * (x - prev));
        prev = x;
        go[(size_t)j*512] = __float2half_rn(st);
    }
}

// -------- LN helpers --------
__global__ __launch_bounds__(256) void ln_sub_kernel(const float* __restrict__ growth,
                                                     const float* __restrict__ g,
                                                     const float* __restrict__ be) {
    int row = blockIdx.x;
    int b = row >> 9, t = row & 511;
    const __half* pa = g_res1h + (size_t)row*512;
    const float*  pb = growth + (size_t)(b*513 + t + 1)*512;
    int tid = threadIdx.x;
    float x0 = __half2float(pa[tid])       - pb[tid];
    float x1 = __half2float(pa[tid + 256]) - pb[tid + 256];
    __shared__ float red[18];
    float s = x0 + x1, q = fmaf(x0, x0, x1*x1);
    int lane = tid & 31, warp = tid >> 5;
    #pragma unroll
    for (int o = 16; o; o >>= 1) { s += __shfl_xor_sync(~0u, s, o); q += __shfl_xor_sync(~0u, q, o); }
    if (lane == 0) { red[warp] = s; red[8 + warp] = q; }
    __syncthreads();
    if (tid < 32) {
        s = (tid < 8) ? red[tid] : 0.f;
        q = (tid < 8) ? red[8 + tid] : 0.f;
        #pragma unroll
        for (int o = 4; o; o >>= 1) { s += __shfl_xor_sync(~0u, s, o); q += __shfl_xor_sync(~0u, q, o); }
        if (tid == 0) {
            float mu = s * (1.f/512.f);
            float var = q * (1.f/512.f) - mu*mu;
            red[16] = mu; red[17] = rsqrtf(var + 1e-5f);
        }
    }
    __syncthreads();
    float mu = red[16], r = red[17];
    float h0  = (x0 - mu)*r*g[tid]       + be[tid];
    float h1v = (x1 - mu)*r*g[tid + 256] + be[tid + 256];
    g_h1h[(size_t)row*512 + tid]       = __float2half_rn(h0);
    g_h1h[(size_t)row*512 + tid + 256] = __float2half_rn(h1v);
}

__global__ __launch_bounds__(256) void ln_add_kernel(const float* __restrict__ g,
                                                     const float* __restrict__ be,
                                                     float* __restrict__ out) {
    int row = blockIdx.x;
    const __half* pa = g_h1h  + (size_t)row*512;
    const __half* pb = g_ff2h + (size_t)row*512;
    int tid = threadIdx.x;
    float x0 = __half2float(pa[tid])       + __half2float(pb[tid]);
    float x1 = __half2float(pa[tid + 256]) + __half2float(pb[tid + 256]);
    __shared__ float red[18];
    float s = x0 + x1, q = fmaf(x0, x0, x1*x1);
    int lane = tid & 31, warp = tid >> 5;
    #pragma unroll
    for (int o = 16; o; o >>= 1) { s += __shfl_xor_sync(~0u, s, o); q += __shfl_xor_sync(~0u, q, o); }
    if (lane == 0) { red[warp] = s; red[8 + warp] = q; }
    __syncthreads();
    if (tid < 32) {
        s = (tid < 8) ? red[tid] : 0.f;
        q = (tid < 8) ? red[8 + tid] : 0.f;
        #pragma unroll
        for (int o = 4; o; o >>= 1) { s += __shfl_xor_sync(~0u, s, o); q += __shfl_xor_sync(~0u, q, o); }
        if (tid == 0) {
            float mu = s * (1.f/512.f);
            float var = q * (1.f/512.f) - mu*mu;
            red[16] = mu; red[17] = rsqrtf(var + 1e-5f);
        }
    }
    __syncthreads();
    float mu = red[16], r = red[17];
    float* po = out + (size_t)row*512;
    po[tid]       = (x0 - mu)*r*g[tid]       + be[tid];
    po[tid + 256] = (x1 - mu)*r*g[tid + 256] + be[tid + 256];
}

// -------- gp/sp projections, 4 rows per block ------------------------------
__global__ __launch_bounds__(256) void proj7_kernel(const float* __restrict__ growth,
                                                    const float* __restrict__ season,
                                                    const float* __restrict__ Wg,
                                                    const float* __restrict__ bg,
                                                    const float* __restrict__ Ws,
                                                    const float* __restrict__ bs) {
    int row0 = blockIdx.x * 4;
    int tid = threadIdx.x;
    __shared__ float gx[4][512], sx[4][512];
    #pragma unroll
    for (int rr = 0; rr < 4; rr++) {
        int row = row0 + rr;
        int b = row >> 9, t = row & 511;
        const float* grow = growth + (size_t)(b*513 + t + 1)*512;
        const float* srow = season + (size_t)(b*608 + t)*512;
        for (int i = tid; i < 512; i += 256) { gx[rr][i] = grow[i]; sx[rr][i] = srow[i]; }
    }
    __syncthreads();
    int warp = tid >> 5, lane = tid & 31;
    for (int task = warp; task < 28; task += 8) {
        int rr = task / 7, c = task - rr*7;
        float s1 = 0.f, s2 = 0.f;
        const float* wg = Wg + c*512;
        const float* ws = Ws + c*512;
        for (int i = lane; i < 512; i += 32) {
            s1 = fmaf(gx[rr][i], wg[i], s1);
            s2 = fmaf(sx[rr][i], ws[i], s2);
        }
        #pragma unroll
        for (int o = 16; o; o >>= 1) {
            s1 += __shfl_xor_sync(~0u, s1, o);
            s2 += __shfl_xor_sync(~0u, s2, o);
        }
        if (lane == 0) {
            int row = row0 + rr;
            g_gp[row*7 + c] = s1 + bg[c];
            g_sp[row*7 + c] = s2 + bs[c];
        }
    }
}

// -------- level EMA with aux: warp-parallel affine scan --------
__global__ __launch_bounds__(256) void level_scan_kernel(const float* __restrict__ level,
                                                         const float* __restrict__ sw_l,
                                                         const float* __restrict__ v0_l,
                                                         float* __restrict__ lvl_out) {
    int w = (blockIdx.x * blockDim.x + threadIdx.x) >> 5;
    int lane = threadIdx.x & 31;
    if (w >= BB * COUTN) return;
    int b = w / COUTN, c = w % COUTN;
    float alpha = 1.f / (1.f + expf(-sw_l[c]));
    float oma = 1.f - alpha;
    float a2 = alpha*alpha, a4 = a2*a2, a8 = a4*a4;
    float P16 = a8*a8;

    int base = (b*512 + lane*16)*COUTN + c;
    float u1[16], u2[16];
    #pragma unroll
    for (int j = 0; j < 16; j++) {
        int idx = base + j*COUTN;
        u1[j] = oma * (level[idx] - g_sp[idx]);
        u2[j] = alpha * g_gp[idx];
    }
    float S1 = 0.f, S2 = 0.f;
    #pragma unroll
    for (int j = 0; j < 16; j++) { S1 = fmaf(alpha, S1, u1[j]); S2 = fmaf(alpha, S2, u2[j]); }
    float P = P16;
    #pragma unroll
    for (int d = 1; d < 32; d <<= 1) {
        float Pp  = __shfl_up_sync(~0u, P,  d);
        float S1p = __shfl_up_sync(~0u, S1, d);
        float S2p = __shfl_up_sync(~0u, S2, d);
        if (lane >= d) { S1 = fmaf(P, S1p, S1); S2 = fmaf(P, S2p, S2); P *= Pp; }
    }
    float Px  = __shfl_up_sync(~0u, P,  1);
    float S1x = __shfl_up_sync(~0u, S1, 1);
    float S2x = __shfl_up_sync(~0u, S2, 1);
    if (lane == 0) { Px = 1.f; S1x = 0.f; S2x = 0.f; }
    float s   = fmaf(Px, v0_l[c], S1x);
    float aux = S2x;
    #pragma unroll
    for (int j = 0; j < 16; j++) {
        s   = fmaf(alpha, s,   u1[j]);
        aux = fmaf(alpha, aux, u2[j]);
        lvl_out[base + j*COUTN] = s + aux;
    }
}

// ---------------- launch ----------------
extern "C" void kernel_launch(void* const* d_in, const int* in_sizes, int n_in,
                              void* d_out, int out_size) {
    const float* res   = (const float*)d_in[0];
    const float* level = (const float*)d_in[1];
    const float* Wi    = (const float*)d_in[2];
    const float* bi    = (const float*)d_in[3];
    const float* z0    = (const float*)d_in[4];
    const float* v0_g  = (const float*)d_in[5];
    const float* sw_g  = (const float*)d_in[6];
    const float* Wo    = (const float*)d_in[7];
    const float* bo    = (const float*)d_in[8];
    const float* W1    = (const float*)d_in[9];
    const float* W2    = (const float*)d_in[10];
    const float* g1    = (const float*)d_in[11];
    const float* b1    = (const float*)d_in[12];
    const float* g2    = (const float*)d_in[13];
    const float* b2    = (const float*)d_in[14];
    const float* Wg    = (const float*)d_in[15];
    const float* bg    = (const float*)d_in[16];
    const float* Ws    = (const float*)d_in[17];
    const float* bs    = (const float*)d_in[18];
    const float* v0_l  = (const float*)d_in[19];
    const float* sw_l  = (const float*)d_in[20];
    float* out = (float*)d_out;

    __half *p_res1h, *p_vh, *p_gr, *p_h1h, *p_ffb, *p_ff2h, *p_Wih, *p_Woh, *p_W1h, *p_W2h;
    cudaGetSymbolAddress((void**)&p_res1h, g_res1h);
    cudaGetSymbolAddress((void**)&p_vh,    g_vh);
    cudaGetSymbolAddress((void**)&p_gr,    g_gr);
    cudaGetSymbolAddress((void**)&p_h1h,   g_h1h);
    cudaGetSymbolAddress((void**)&p_ffb,   g_ffb);
    cudaGetSymbolAddress((void**)&p_ff2h,  g_ff2h);
    cudaGetSymbolAddress((void**)&p_Wih,   g_Wih);
    cudaGetSymbolAddress((void**)&p_Woh,   g_Woh);
    cudaGetSymbolAddress((void**)&p_W1h,   g_W1h);
    cudaGetSymbolAddress((void**)&p_W2h,   g_W2h);

    cudaFuncSetAttribute(hgemm<false,true,true>,  cudaFuncAttributeMaxDynamicSharedMemorySize, G_SMEM_DYN);
    cudaFuncSetAttribute(hgemm<false,true,false>, cudaFuncAttributeMaxDynamicSharedMemorySize, G_SMEM_DYN);
    cudaFuncSetAttribute(hgemm<true,false,true>,  cudaFuncAttributeMaxDynamicSharedMemorySize, G_SMEM_DYN);
    cudaFuncSetAttribute(hgemm<false,false,true>, cudaFuncAttributeMaxDynamicSharedMemorySize, G_SMEM_DYN);
    cudaFuncSetAttribute(dft_split_hgemm,         cudaFuncAttributeMaxDynamicSharedMemorySize, DFT_SMEM_DYN);

    float* out_season = out + OFF_SEASON;
    float* out_growth = out + OFF_GROWTH;
    float* out_lvl    = out + OFF_LVL;

    // 1. fused prep (transpose/split + basis + weight f2h)
    prep_kernel<<<7680, 256>>>(res, (const float4*)Wi, (const float4*)Wo,
                               (const float4*)W1, (const float4*)W2);
    // 2. DFT on tensor cores (split-fp16, R8 config)
    dft_split_hgemm<<<dim3(4, 64), 256, DFT_SMEM_DYN>>>();
    // 3. top-16 per (b,d)
    topk_kernel<<<NBD/8, 256>>>();
    // 4. season + res1h
    season_kernel<<<dim3(32, 19), 256>>>(res, out_season);
    // 5. v = res1 @ Wi^T + bi  -> fp16
    hgemm<false,true,true><<<dim3(4, 64), 256, G_SMEM_DYN>>>(p_res1h, p_Wih, bi, nullptr, p_vh, NROW, 512, 512);
    // 6. growth EMA scan (fp16 v)
    growth_ema_scan<<<128, 256>>>(z0, v0_g, sw_g);
    // 7. growth = gr @ Wo^T + bo -> d_out (fp32)
    hgemm<false,true,false><<<dim3(4, 65), 256, G_SMEM_DYN>>>(p_gr, p_Woh, bo, out_growth, nullptr, NROWG, 512, 512);
    // 8. h1 = LN(res1 - growth[:,1:]) -> fp16
    ln_sub_kernel<<<NROW, 256>>>(out_growth, g1, b1);
    // 9. ffb = relu(h1 @ W1^T) -> fp16
    hgemm<true,false,true><<<dim3(16, 64), 256, G_SMEM_DYN>>>(p_h1h, p_W1h, nullptr, nullptr, p_ffb, NROW, DFFN, 512);
    // 10. ff2 = ffb @ W2^T -> fp16
    hgemm<false,false,true><<<dim3(4, 64), 256, G_SMEM_DYN>>>(p_ffb, p_W2h, nullptr, nullptr, p_ff2h, NROW, 512, DFFN);
    // 11. h = LN(h1 + ff2) -> d_out
    ln_add_kernel<<<NROW, 256>>>(g2, b2, out + OFF_H);
    // 12. gp/sp projections (4 rows/block)
    proj7_kernel<<<NROW/4, 256>>>(out_growth, out_season, Wg, bg, Ws, bs);
    // 13. level EMA (warp affine scan) -> d_out
    level_scan_kernel<<<(BB*COUTN*32 + 255)/256, 256>>>(level, sw_l, v0_l, out_lvl);
}

// round 16
// speedup vs baseline: 1.0019x; 1.0004x over previous
#include <cuda_runtime.h>
#include <cuda_fp16.h>
#include <math.h>
#include <cstdint>

// ---------------- problem constants ----------------
#define BB    16
#define TT_   512
#define DD    512
#define COUTN 7
#define DFFN  2048
#define NROW  (BB*TT_)     // 8192
#define NROWG (BB*513)     // 8208
#define NBD   (BB*DD)      // 8192 series for fourier

// output tuple layout: (h, lvl, growth, season) flattened fp32
#define OFF_H      0
#define OFF_LVL    ((size_t)BB*TT_*DD)                 // 4194304
#define OFF_GROWTH (OFF_LVL + (size_t)BB*TT_*COUTN)    // 4251648
#define OFF_SEASON (OFF_GROWTH + (size_t)BB*513*DD)    // 8454144

// ---------------- scratch (__device__ globals; no allocs) ----------------
__device__ float  g_cosT [256*512];
__device__ float  g_sinT [256*512];
__device__ __half g_Bhi[512*512];
__device__ __half g_Blo[512*512];
__device__ __half g_AThi[(size_t)NBD*512];
__device__ __half g_ATlo[(size_t)NBD*512];
__device__ float  g_X[(size_t)NBD*512];      // [bd][0:256)=re, [256:512)=im
__device__ int    g_kidx[16*NBD];
__device__ float  g_ar[16*NBD];
__device__ float  g_ai[16*NBD];
__device__ __half g_res1h[(size_t)NROW*DD];
__device__ __half g_vh[(size_t)NROW*DD];
__device__ __half g_gr[(size_t)NROWG*DD];
__device__ __half g_h1h[(size_t)NROW*DD];
__device__ __half g_ffb[(size_t)NROW*DFFN];
__device__ __half g_ff2h[(size_t)NROW*DD];
__device__ float  g_gp[NROW*COUTN];
__device__ float  g_sp[NROW*COUTN];
// fp16 weights
__device__ __half g_Wih[512*512];
__device__ __half g_Woh[512*512];
__device__ __half g_W1h[2048*512];
__device__ __half g_W2h[512*2048];

// ---------------- common helpers ----------------
__device__ __forceinline__ uint32_t smem_u32(const void* p) {
    uint32_t a;
    asm("{ .reg .u64 t; cvta.to.shared.u64 t, %1; cvt.u32.u64 %0, t; }" : "=r"(a) : "l"(p));
    return a;
}
__device__ __forceinline__ void cp16(uint32_t dst, const void* src) {
    asm volatile("cp.async.cg.shared.global [%0], [%1], 16;"
                 :: "r"(dst), "l"(__cvta_generic_to_global(src)) : "memory");
}
#define CP_COMMIT() asm volatile("cp.async.commit_group;" ::: "memory")
#define CP_WAIT1()  asm volatile("cp.async.wait_group 1;" ::: "memory")

#define LDSM_X4(r0, r1, r2, r3, addr) \
    asm volatile("ldmatrix.sync.aligned.m8n8.x4.shared.b16 {%0,%1,%2,%3}, [%4];" \
        : "=r"(r0), "=r"(r1), "=r"(r2), "=r"(r3) : "r"(addr))

#define MMA_F16(c, a, b) \
    asm volatile("mma.sync.aligned.m16n8k16.row.col.f32.f16.f16.f32 " \
        "{%0,%1,%2,%3}, {%4,%5,%6,%7}, {%8,%9}, {%0,%1,%2,%3};" \
        : "+f"((c)[0]), "+f"((c)[1]), "+f"((c)[2]), "+f"((c)[3]) \
        : "r"((a)[0]), "r"((a)[1]), "r"((a)[2]), "r"((a)[3]), \
          "r"((b)[0]), "r"((b)[1]))

// ============== fp16 HMMA GEMM: C[M,N] = A[M,K] @ W[N,K]^T =============
// block 128x128, K-chunk 64 halves, 8 warps (2x4), cp.async 3-stage, 2 CTA/SM.
#define G_SMEM_DYN (3*32768)

template<bool RELU, bool BIAS, bool HALF_OUT>
__global__ __launch_bounds__(256, 2)
void hgemm(const __half* __restrict__ A, const __half* __restrict__ W,
           const float* __restrict__ bias, float* __restrict__ C,
           __half* __restrict__ Ch, int M, int N, int K)
{
    extern __shared__ char smraw[];
    const uint32_t smem = smem_u32(smraw);
    const int tid  = threadIdx.x;
    const int bm   = blockIdx.y * 128;
    const int bn   = blockIdx.x * 128;
    const int lane = tid & 31;
    const int w    = tid >> 5;
    const int m_base = (w >> 2) * 64;
    const int n_base = (w & 3) * 32;

    int str[4], stg[4];
    #pragma unroll
    for (int i = 0; i < 4; i++) {
        int gid = tid + 256 * i;
        str[i] = gid >> 3;
        stg[i] = gid & 7;
    }

    const int rowA  = m_base + (lane & 15);
    const uint32_t cxA = (uint32_t)(rowA & 7);
    const uint32_t gA  = (uint32_t)(lane >> 4);
    uint32_t rowOffA[4];
    #pragma unroll
    for (int mi = 0; mi < 4; mi++) rowOffA[mi] = (uint32_t)(rowA + mi*16) << 7;

    const uint32_t cxB = (uint32_t)(lane & 7);
    const uint32_t gB  = (uint32_t)((lane >> 3) & 1);
    uint32_t rowOffB[2];
    #pragma unroll
    for (int p = 0; p < 2; p++) {
        int rowB = n_base + p*16 + (lane & 7) + ((lane >> 4) << 3);
        rowOffB[p] = (uint32_t)rowB << 7;
    }

    float acc[4][4][4];
    #pragma unroll
    for (int mi = 0; mi < 4; mi++)
        #pragma unroll
        for (int nj = 0; nj < 4; nj++)
            #pragma unroll
            for (int e = 0; e < 4; e++) acc[mi][nj][e] = 0.f;

    const int nch = K >> 6;

    auto issue = [&](int c) {
        const int k0 = c << 6;
        const uint32_t st  = smem + (uint32_t)(c % 3) * 32768;
        const uint32_t stB = st + 16384;
        #pragma unroll
        for (int i = 0; i < 4; i++) {
            uint32_t off = ((uint32_t)str[i] << 7) + (uint32_t)((stg[i] ^ (str[i] & 7)) << 4);
            int rm = bm + str[i]; if (rm > M - 1) rm = M - 1;
            cp16(st  + off, A + (size_t)rm * K + k0 + stg[i]*8);
            cp16(stB + off, W + (size_t)(bn + str[i]) * K + k0 + stg[i]*8);
        }
        CP_COMMIT();
    };
    auto compute_chunk = [&](int s) {
        const uint32_t stA = smem + (uint32_t)s * 32768;
        const uint32_t stB = stA + 16384;
        #pragma unroll
        for (int k16 = 0; k16 < 4; k16++) {
            uint32_t a[4][4];
            #pragma unroll
            for (int mi = 0; mi < 4; mi++) {
                uint32_t ad = stA + rowOffA[mi] + ((((uint32_t)(k16*2) + gA) ^ cxA) << 4);
                LDSM_X4(a[mi][0], a[mi][1], a[mi][2], a[mi][3], ad);
            }
            uint32_t b[4][2];
            #pragma unroll
            for (int p = 0; p < 2; p++) {
                uint32_t bd = stB + rowOffB[p] + ((((uint32_t)(k16*2) + gB) ^ cxB) << 4);
                LDSM_X4(b[2*p][0], b[2*p][1], b[2*p+1][0], b[2*p+1][1], bd);
            }
            #pragma unroll
            for (int mi = 0; mi < 4; mi++)
                #pragma unroll
                for (int nj = 0; nj < 4; nj++)
                    MMA_F16(acc[mi][nj], a[mi], b[nj]);
        }
    };

    issue(0);
    if (nch > 1) issue(1);

    for (int c = 0; c < nch; c++) {
        CP_WAIT1();
        __syncthreads();
        if (c + 2 < nch) issue(c + 2);
        compute_chunk(c % 3);
    }

    #pragma unroll
    for (int mi = 0; mi < 4; mi++) {
        const int r0 = bm + m_base + mi*16 + (lane >> 2);
        const int r1 = r0 + 8;
        #pragma unroll
        for (int nj = 0; nj < 4; nj++) {
            const int col = bn + n_base + nj*8 + (lane & 3)*2;
            float2 v0 = make_float2(acc[mi][nj][0], acc[mi][nj][1]);
            float2 v1 = make_float2(acc[mi][nj][2], acc[mi][nj][3]);
            if (BIAS) {
                float bx = bias[col], by = bias[col + 1];
                v0.x += bx; v0.y += by; v1.x += bx; v1.y += by;
            }
            if (RELU) {
                v0.x = fmaxf(v0.x, 0.f); v0.y = fmaxf(v0.y, 0.f);
                v1.x = fmaxf(v1.x, 0.f); v1.y = fmaxf(v1.y, 0.f);
            }
            if (HALF_OUT) {
                if (r0 < M) *(__half2*)(Ch + (size_t)r0 * N + col) = __floats2half2_rn(v0.x, v0.y);
                if (r1 < M) *(__half2*)(Ch + (size_t)r1 * N + col) = __floats2half2_rn(v1.x, v1.y);
            } else {
                if (r0 < M) *(float2*)(C + (size_t)r0 * N + col) = v0;
                if (r1 < M) *(float2*)(C + (size_t)r1 * N + col) = v1;
            }
        }
    }
}

// ====== split-fp16 DFT GEMM (R8 config): X = AT @ B^T, 64KB stages =========
#define DFT_SMEM_DYN (3*65536)

__global__ __launch_bounds__(256)
void dft_split_hgemm()
{
    extern __shared__ char smraw[];
    const uint32_t smem = smem_u32(smraw);
    const __half* __restrict__ Ahi = g_AThi;
    const __half* __restrict__ Alo = g_ATlo;
    const __half* __restrict__ Bhi = g_Bhi;
    const __half* __restrict__ Blo = g_Blo;
    const int tid  = threadIdx.x;
    const int bm   = blockIdx.y * 128;
    const int bn   = blockIdx.x * 128;
    const int lane = tid & 31;
    const int w    = tid >> 5;
    const int m_base = (w >> 2) * 64;
    const int n_base = (w & 3) * 32;

    int str[4], stg[4];
    #pragma unroll
    for (int i = 0; i < 4; i++) {
        int gid = tid + 256 * i;
        str[i] = gid >> 3;
        stg[i] = gid & 7;
    }

    const int rowA  = m_base + (lane & 15);
    const uint32_t cxA = (uint32_t)(rowA & 7);
    const uint32_t gA  = (uint32_t)(lane >> 4);
    uint32_t rowOffA[4];
    #pragma unroll
    for (int mi = 0; mi < 4; mi++) rowOffA[mi] = (uint32_t)(rowA + mi*16) << 7;

    const uint32_t cxB = (uint32_t)(lane & 7);
    const uint32_t gB  = (uint32_t)((lane >> 3) & 1);
    uint32_t rowOffB[2];
    #pragma unroll
    for (int p = 0; p < 2; p++) {
        int rowB = n_base + p*16 + (lane & 7) + ((lane >> 4) << 3);
        rowOffB[p] = (uint32_t)rowB << 7;
    }

    float acc[4][4][4];
    #pragma unroll
    for (int mi = 0; mi < 4; mi++)
        #pragma unroll
        for (int nj = 0; nj < 4; nj++)
            #pragma unroll
            for (int e = 0; e < 4; e++) acc[mi][nj][e] = 0.f;

    const int nch = 8;

    auto issue = [&](int c) {
        const int k0 = c << 6;
        const uint32_t st = smem + (uint32_t)(c % 3) * 65536;
        #pragma unroll
        for (int i = 0; i < 4; i++) {
            uint32_t off = ((uint32_t)str[i] << 7) + (uint32_t)((stg[i] ^ (str[i] & 7)) << 4);
            size_t offA = (size_t)(bm + str[i]) * 512 + k0 + stg[i]*8;
            size_t offB = (size_t)(bn + str[i]) * 512 + k0 + stg[i]*8;
            cp16(st + off,         Ahi + offA);
            cp16(st + 16384 + off, Alo + offA);
            cp16(st + 32768 + off, Bhi + offB);
            cp16(st + 49152 + off, Blo + offB);
        }
        CP_COMMIT();
    };
    auto compute_chunk = [&](int s) {
        const uint32_t st = smem + (uint32_t)s * 65536;
        #pragma unroll
        for (int k16 = 0; k16 < 4; k16++) {
            uint32_t aH[4][4], aL[4][4];
            #pragma unroll
            for (int mi = 0; mi < 4; mi++) {
                uint32_t xo = rowOffA[mi] + ((((uint32_t)(k16*2) + gA) ^ cxA) << 4);
                LDSM_X4(aH[mi][0], aH[mi][1], aH[mi][2], aH[mi][3], st + xo);
                LDSM_X4(aL[mi][0], aL[mi][1], aL[mi][2], aL[mi][3], st + 16384 + xo);
            }
            uint32_t bH[4][2], bL[4][2];
            #pragma unroll
            for (int p = 0; p < 2; p++) {
                uint32_t xo = rowOffB[p] + ((((uint32_t)(k16*2) + gB) ^ cxB) << 4);
                LDSM_X4(bH[2*p][0], bH[2*p][1], bH[2*p+1][0], bH[2*p+1][1], st + 32768 + xo);
                LDSM_X4(bL[2*p][0], bL[2*p][1], bL[2*p+1][0], bL[2*p+1][1], st + 49152 + xo);
            }
            #pragma unroll
            for (int mi = 0; mi < 4; mi++)
                #pragma unroll
                for (int nj = 0; nj < 4; nj++) {
                    MMA_F16(acc[mi][nj], aL[mi], bH[nj]);
                    MMA_F16(acc[mi][nj], aH[mi], bL[nj]);
                    MMA_F16(acc[mi][nj], aH[mi], bH[nj]);
                }
        }
    };

    issue(0);
    issue(1);

    for (int c = 0; c < nch; c++) {
        CP_WAIT1();
        __syncthreads();
        if (c + 2 < nch) issue(c + 2);
        compute_chunk(c % 3);
    }

    #pragma unroll
    for (int mi = 0; mi < 4; mi++) {
        const int r0 = bm + m_base + mi*16 + (lane >> 2);
        const int r1 = r0 + 8;
        #pragma unroll
        for (int nj = 0; nj < 4; nj++) {
            const int col = bn + n_base + nj*8 + (lane & 3)*2;
            *(float2*)(g_X + (size_t)r0 * 512 + col) = make_float2(acc[mi][nj][0], acc[mi][nj][1]);
            *(float2*)(g_X + (size_t)r1 * 512 + col) = make_float2(acc[mi][nj][2], acc[mi][nj][3]);
        }
    }
}

// ------- fused prep: transpose/split + basis tables + weight f2h -----------
// blocks [0,4096): transpose res -> AT hi/lo
// blocks [4096,5120): basis tables (cos/sin + DFT basis hi/lo)
// blocks [5120,7680): weight fp32->fp16
__global__ __launch_bounds__(256) void prep_kernel(const float* __restrict__ res,
                                                   const float4* __restrict__ Wi,
                                                   const float4* __restrict__ Wo,
                                                   const float4* __restrict__ W1,
                                                   const float4* __restrict__ W2) {
    int blk = blockIdx.x;
    int tid = threadIdx.x;
    if (blk < 4096) {
        __shared__ float tile[32][33];
        int b  = blk >> 8;
        int d0 = ((blk >> 4) & 15) * 32;
        int t0 = (blk & 15) * 32;
        int x = tid & 31, y = tid >> 5;
        const float* src = res + (size_t)b * 512 * 512;
        #pragma unroll
        for (int i = 0; i < 32; i += 8)
            tile[y + i][x] = src[(size_t)(t0 + y + i) * 512 + d0 + x];
        __syncthreads();
        #pragma unroll
        for (int i = 0; i < 32; i += 8) {
            float v = tile[x][y + i];
            __half hi = __float2half_rn(v);
            size_t idx = (size_t)(b*512 + d0 + y + i) * 512 + t0 + x;
            g_AThi[idx] = hi;
            g_ATlo[idx] = __float2half_rn(v - __half2float(hi));
        }
    } else if (blk < 5120) {
        int e = (blk - 4096) * 256 + tid;   // 0..262143
        int n = e >> 9;
        int t = e & 511;
        int k = n & 255;
        int m = (k * t) & 511;
        float ang = 6.283185307179586f * (float)m * (1.0f/512.0f);
        float s, c;
        sincosf(ang, &s, &c);
        if (n < 256) {
            g_cosT[n*512 + t] = c;
            g_sinT[n*512 + t] = s;
        }
        float val = (n < 256) ? c : -s;
        __half hi = __float2half_rn(val);
        g_Bhi[n*512 + t] = hi;
        g_Blo[n*512 + t] = __float2half_rn(val - __half2float(hi));
    } else {
        int i = (blk - 5120) * 256 + tid;   // 0..655359
        const float4* src; __half2* dst; int off;
        if (i < 65536)       { src = Wi; dst = (__half2*)g_Wih; off = i; }
        else if (i < 131072) { src = Wo; dst = (__half2*)g_Woh; off = i - 65536; }
        else if (i < 393216) { src = W1; dst = (__half2*)g_W1h; off = i - 131072; }
        else                 { src = W2; dst = (__half2*)g_W2h; off = i - 393216; }
        float4 v = src[off];
        __half2 h0 = __floats2half2_rn(v.x, v.y);
        __half2 h1 = __floats2half2_rn(v.z, v.w);
        uint2 pk = make_uint2(*(uint32_t*)&h0, *(uint32_t*)&h1);
        *(uint2*)(dst + 2*off) = pk;
    }
}

// -------- top-16 |X|^2 over k in [1,255]: sorted-lane tournament -----------
__global__ __launch_bounds__(256) void topk_kernel() {
    int warp = threadIdx.x >> 5, lane = threadIdx.x & 31;
    int bd = blockIdx.x * 8 + warp;
    const float* xr = g_X + (size_t)bd*512;
    const float* xi = xr + 256;

    unsigned long long key[8];
    #pragma unroll
    for (int j = 0; j < 8; j++) {
        int k = 1 + lane + 32*j;
        if (k <= 255) {
            float r = xr[k], q = xi[k];
            float m2 = fmaf(r, r, q*q);
            key[j] = ((unsigned long long)__float_as_uint(m2) << 32)
                   | (unsigned long long)(511 - k);
        } else key[j] = 0ull;
    }
    #define CSW(a_, b_) { unsigned long long hi_ = key[a_] > key[b_] ? key[a_] : key[b_]; \
                          unsigned long long lo_ = key[a_] > key[b_] ? key[b_] : key[a_]; \
                          key[a_] = hi_; key[b_] = lo_; }
    CSW(0,1) CSW(2,3) CSW(4,5) CSW(6,7)
    CSW(0,2) CSW(1,3) CSW(4,6) CSW(5,7)
    CSW(1,2) CSW(5,6)
    CSW(0,4) CSW(1,5) CSW(2,6) CSW(3,7)
    CSW(2,4) CSW(3,5)
    CSW(1,2) CSW(3,4) CSW(5,6)
    #undef CSW

    #pragma unroll 1
    for (int r = 0; r < 16; r++) {
        unsigned long long cur = key[0];
        unsigned long long m = cur;
        #pragma unroll
        for (int off = 16; off; off >>= 1) {
            unsigned long long o = __shfl_xor_sync(0xffffffffu, m, off);
            if (o > m) m = o;
        }
        if (cur == m) {
            #pragma unroll
            for (int i = 0; i < 7; i++) key[i] = key[i+1];
            key[7] = 0ull;
        }
        if (lane == 0) {
            int k = 511 - (int)(m & 0xffffffffull);
            g_kidx[r*NBD + bd] = k;
            g_ar[r*NBD + bd] = xr[k] * (2.0f/512.0f);
            g_ai[r*NBD + bd] = xi[k] * (2.0f/512.0f);
        }
    }
}

// ------- season synthesis (4-way rotation interleave) + res1h --------------
__global__ __launch_bounds__(256) void season_kernel(const float* __restrict__ res,
                                                     float* __restrict__ season) {
    int bd = blockIdx.x * 256 + threadIdx.x;
    int tt0 = blockIdx.y * 32;
    int b = bd >> 9, d = bd & 511;

    float acc[32];
    #pragma unroll
    for (int i = 0; i < 32; i++) acc[i] = 0.f;

    for (int j = 0; j < 16; j += 4) {
        float c[4], s[4], cd[4], sd[4], ar[4], ai[4];
        #pragma unroll
        for (int q = 0; q < 4; q++) {
            int   k = g_kidx[(j+q)*NBD + bd];
            ar[q] = g_ar[(j+q)*NBD + bd];
            ai[q] = g_ai[(j+q)*NBD + bd];
            int m = (k * tt0) & 511;
            c[q]  = g_cosT[512 + m];  s[q]  = g_sinT[512 + m];
            cd[q] = g_cosT[512 + k];  sd[q] = g_sinT[512 + k];
        }
        #pragma unroll
        for (int i = 0; i < 32; i++) {
            #pragma unroll
            for (int q = 0; q < 4; q++) {
                acc[i] = fmaf(ar[q], c[q], fmaf(-ai[q], s[q], acc[i]));
                float cn = fmaf(c[q], cd[q], -s[q]*sd[q]);
                s[q] = fmaf(s[q], cd[q], c[q]*sd[q]);
                c[q] = cn;
            }
        }
    }
    #pragma unroll
    for (int i = 0; i < 32; i++) {
        int tt = tt0 + i;
        float v = acc[i];
        season[((size_t)(b*608 + tt))*512 + d] = v;
        if (tt < 512) {
            size_t idx = ((size_t)(b*512 + tt))*512 + d;
            g_res1h[idx] = __float2half_rn(res[idx] - v);
        }
    }
}

// -------- growth EMA as 4-way affine scan (fp16 v input) -------------------
__global__ __launch_bounds__(256) void growth_ema_scan(const float* __restrict__ z0,
                                                       const float* __restrict__ v0g,
                                                       const float* __restrict__ sw_g) {
    int blk = blockIdx.x;
    int b   = blk >> 3;
    int hd0 = (blk & 7) << 6;
    int s   = threadIdx.x & 63;
    int q   = threadIdx.x >> 6;
    int hd  = hd0 + s;
    int h   = hd >> 6;
    float alpha = 1.f / (1.f + expf(-sw_g[h]));
    float oma = 1.f - alpha;
    float A = alpha;
    #pragma unroll
    for (int i = 0; i < 7; i++) A *= A;

    const __half* vcol = g_vh + (size_t)b*512*512 + hd;
    const int t0 = q << 7;

    float prev0 = (q == 0) ? z0[hd] : __half2float(vcol[(size_t)(t0 - 1)*512]);
    float prev = prev0;
    float S = 0.f;
    for (int j = 0; j < 128; j++) {
        float x = __half2float(vcol[(size_t)(t0 + j)*512]);
        S = fmaf(alpha, S, oma * (x - prev));
        prev = x;
    }
    __shared__ float Ss[4][64];
    Ss[q][s] = S;
    __syncthreads();

    float E = v0g[hd];
    for (int p = 0; p < q; p++) E = fmaf(A, E, Ss[p][s]);

    prev = prev0;
    float st = E;
    __half* go = g_gr + ((size_t)(b*513 + 1 + t0))*512 + hd;
    if (q == 0) g_gr[((size_t)(b*513))*512 + hd] = __float2half_rn(E);
    for (int j = 0; j < 128; j++) {
        float x = __half2float(vcol[(size_t)(t0 + j)*512]);
        st = fmaf(alpha, st, oma * (x - prev));
        prev = x;
        go[(size_t)j*512] = __float2half_rn(st);
    }
}

// -------- LN helpers --------
__global__ __launch_bounds__(256) void ln_sub_kernel(const float* __restrict__ growth,
                                                     const float* __restrict__ g,
                                                     const float* __restrict__ be) {
    int row = blockIdx.x;
    int b = row >> 9, t = row & 511;
    const __half* pa = g_res1h + (size_t)row*512;
    const float*  pb = growth + (size_t)(b*513 + t + 1)*512;
    int tid = threadIdx.x;
    float x0 = __half2float(pa[tid])       - pb[tid];
    float x1 = __half2float(pa[tid + 256]) - pb[tid + 256];
    __shared__ float red[18];
    float s = x0 + x1, q = fmaf(x0, x0, x1*x1);
    int lane = tid & 31, warp = tid >> 5;
    #pragma unroll
    for (int o = 16; o; o >>= 1) { s += __shfl_xor_sync(~0u, s, o); q += __shfl_xor_sync(~0u, q, o); }
    if (lane == 0) { red[warp] = s; red[8 + warp] = q; }
    __syncthreads();
    if (tid < 32) {
        s = (tid < 8) ? red[tid] : 0.f;
        q = (tid < 8) ? red[8 + tid] : 0.f;
        #pragma unroll
        for (int o = 4; o; o >>= 1) { s += __shfl_xor_sync(~0u, s, o); q += __shfl_xor_sync(~0u, q, o); }
        if (tid == 0) {
            float mu = s * (1.f/512.f);
            float var = q * (1.f/512.f) - mu*mu;
            red[16] = mu; red[17] = rsqrtf(var + 1e-5f);
        }
    }
    __syncthreads();
    float mu = red[16], r = red[17];
    float h0  = (x0 - mu)*r*g[tid]       + be[tid];
    float h1v = (x1 - mu)*r*g[tid + 256] + be[tid + 256];
    g_h1h[(size_t)row*512 + tid]       = __float2half_rn(h0);
    g_h1h[(size_t)row*512 + tid + 256] = __float2half_rn(h1v);
}

__global__ __launch_bounds__(256) void ln_add_kernel(const float* __restrict__ g,
                                                     const float* __restrict__ be,
                                                     float* __restrict__ out) {
    int row = blockIdx.x;
    const __half* pa = g_h1h  + (size_t)row*512;
    const __half* pb = g_ff2h + (size_t)row*512;
    int tid = threadIdx.x;
    float x0 = __half2float(pa[tid])       + __half2float(pb[tid]);
    float x1 = __half2float(pa[tid + 256]) + __half2float(pb[tid + 256]);
    __shared__ float red[18];
    float s = x0 + x1, q = fmaf(x0, x0, x1*x1);
    int lane = tid & 31, warp = tid >> 5;
    #pragma unroll
    for (int o = 16; o; o >>= 1) { s += __shfl_xor_sync(~0u, s, o); q += __shfl_xor_sync(~0u, q, o); }
    if (lane == 0) { red[warp] = s; red[8 + warp] = q; }
    __syncthreads();
    if (tid < 32) {
        s = (tid < 8) ? red[tid] : 0.f;
        q = (tid < 8) ? red[8 + tid] : 0.f;
        #pragma unroll
        for (int o = 4; o; o >>= 1) { s += __shfl_xor_sync(~0u, s, o); q += __shfl_xor_sync(~0u, q, o); }
        if (tid == 0) {
            float mu = s * (1.f/512.f);
            float var = q * (1.f/512.f) - mu*mu;
            red[16] = mu; red[17] = rsqrtf(var + 1e-5f);
        }
    }
    __syncthreads();
    float mu = red[16], r = red[17];
    float* po = out + (size_t)row*512;
    po[tid]       = (x0 - mu)*r*g[tid]       + be[tid];
    po[tid + 256] = (x1 - mu)*r*g[tid + 256] + be[tid + 256];
}

// -------- gp/sp projections, 4 rows per block ------------------------------
__global__ __launch_bounds__(256) void proj7_kernel(const float* __restrict__ growth,
                                                    const float* __restrict__ season,
                                                    const float* __restrict__ Wg,
                                                    const float* __restrict__ bg,
                                                    const float* __restrict__ Ws,
                                                    const float* __restrict__ bs) {
    int row0 = blockIdx.x * 4;
    int tid = threadIdx.x;
    __shared__ float gx[4][512], sx[4][512];
    #pragma unroll
    for (int rr = 0; rr < 4; rr++) {
        int row = row0 + rr;
        int b = row >> 9, t = row & 511;
        const float* grow = growth + (size_t)(b*513 + t + 1)*512;
        const float* srow = season + (size_t)(b*608 + t)*512;
        for (int i = tid; i < 512; i += 256) { gx[rr][i] = grow[i]; sx[rr][i] = srow[i]; }
    }
    __syncthreads();
    int warp = tid >> 5, lane = tid & 31;
    for (int task = warp; task < 28; task += 8) {
        int rr = task / 7, c = task - rr*7;
        float s1 = 0.f, s2 = 0.f;
        const float* wg = Wg + c*512;
        const float* ws = Ws + c*512;
        for (int i = lane; i < 512; i += 32) {
            s1 = fmaf(gx[rr][i], wg[i], s1);
            s2 = fmaf(sx[rr][i], ws[i], s2);
        }
        #pragma unroll
        for (int o = 16; o; o >>= 1) {
            s1 += __shfl_xor_sync(~0u, s1, o);
            s2 += __shfl_xor_sync(~0u, s2, o);
        }
        if (lane == 0) {
            int row = row0 + rr;
            g_gp[row*7 + c] = s1 + bg[c];
            g_sp[row*7 + c] = s2 + bs[c];
        }
    }
}

// -------- level EMA with aux: warp-parallel affine scan --------
__global__ __launch_bounds__(256) void level_scan_kernel(const float* __restrict__ level,
                                                         const float* __restrict__ sw_l,
                                                         const float* __restrict__ v0_l,
                                                         float* __restrict__ lvl_out) {
    int w = (blockIdx.x * blockDim.x + threadIdx.x) >> 5;
    int lane = threadIdx.x & 31;
    if (w >= BB * COUTN) return;
    int b = w / COUTN, c = w % COUTN;
    float alpha = 1.f / (1.f + expf(-sw_l[c]));
    float oma = 1.f - alpha;
    float a2 = alpha*alpha, a4 = a2*a2, a8 = a4*a4;
    float P16 = a8*a8;

    int base = (b*512 + lane*16)*COUTN + c;
    float u1[16], u2[16];
    #pragma unroll
    for (int j = 0; j < 16; j++) {
        int idx = base + j*COUTN;
        u1[j] = oma * (level[idx] - g_sp[idx]);
        u2[j] = alpha * g_gp[idx];
    }
    float S1 = 0.f, S2 = 0.f;
    #pragma unroll
    for (int j = 0; j < 16; j++) { S1 = fmaf(alpha, S1, u1[j]); S2 = fmaf(alpha, S2, u2[j]); }
    float P = P16;
    #pragma unroll
    for (int d = 1; d < 32; d <<= 1) {
        float Pp  = __shfl_up_sync(~0u, P,  d);
        float S1p = __shfl_up_sync(~0u, S1, d);
        float S2p = __shfl_up_sync(~0u, S2, d);
        if (lane >= d) { S1 = fmaf(P, S1p, S1); S2 = fmaf(P, S2p, S2); P *= Pp; }
    }
    float Px  = __shfl_up_sync(~0u, P,  1);
    float S1x = __shfl_up_sync(~0u, S1, 1);
    float S2x = __shfl_up_sync(~0u, S2, 1);
    if (lane == 0) { Px = 1.f; S1x = 0.f; S2x = 0.f; }
    float s   = fmaf(Px, v0_l[c], S1x);
    float aux = S2x;
    #pragma unroll
    for (int j = 0; j < 16; j++) {
        s   = fmaf(alpha, s,   u1[j]);
        aux = fmaf(alpha, aux, u2[j]);
        lvl_out[base + j*COUTN] = s + aux;
    }
}

// ---------------- launch ----------------
extern "C" void kernel_launch(void* const* d_in, const int* in_sizes, int n_in,
                              void* d_out, int out_size) {
    const float* res   = (const float*)d_in[0];
    const float* level = (const float*)d_in[1];
    const float* Wi    = (const float*)d_in[2];
    const float* bi    = (const float*)d_in[3];
    const float* z0    = (const float*)d_in[4];
    const float* v0_g  = (const float*)d_in[5];
    const float* sw_g  = (const float*)d_in[6];
    const float* Wo    = (const float*)d_in[7];
    const float* bo    = (const float*)d_in[8];
    const float* W1    = (const float*)d_in[9];
    const float* W2    = (const float*)d_in[10];
    const float* g1    = (const float*)d_in[11];
    const float* b1    = (const float*)d_in[12];
    const float* g2    = (const float*)d_in[13];
    const float* b2    = (const float*)d_in[14];
    const float* Wg    = (const float*)d_in[15];
    const float* bg    = (const float*)d_in[16];
    const float* Ws    = (const float*)d_in[17];
    const float* bs    = (const float*)d_in[18];
    const float* v0_l  = (const float*)d_in[19];
    const float* sw_l  = (const float*)d_in[20];
    float* out = (float*)d_out;

    __half *p_res1h, *p_vh, *p_gr, *p_h1h, *p_ffb, *p_ff2h, *p_Wih, *p_Woh, *p_W1h, *p_W2h;
    cudaGetSymbolAddress((void**)&p_res1h, g_res1h);
    cudaGetSymbolAddress((void**)&p_vh,    g_vh);
    cudaGetSymbolAddress((void**)&p_gr,    g_gr);
    cudaGetSymbolAddress((void**)&p_h1h,   g_h1h);
    cudaGetSymbolAddress((void**)&p_ffb,   g_ffb);
    cudaGetSymbolAddress((void**)&p_ff2h,  g_ff2h);
    cudaGetSymbolAddress((void**)&p_Wih,   g_Wih);
    cudaGetSymbolAddress((void**)&p_Woh,   g_Woh);
    cudaGetSymbolAddress((void**)&p_W1h,   g_W1h);
    cudaGetSymbolAddress((void**)&p_W2h,   g_W2h);

    cudaFuncSetAttribute(hgemm<false,true,true>,  cudaFuncAttributeMaxDynamicSharedMemorySize, G_SMEM_DYN);
    cudaFuncSetAttribute(hgemm<false,true,false>, cudaFuncAttributeMaxDynamicSharedMemorySize, G_SMEM_DYN);
    cudaFuncSetAttribute(hgemm<true,false,true>,  cudaFuncAttributeMaxDynamicSharedMemorySize, G_SMEM_DYN);
    cudaFuncSetAttribute(hgemm<false,false,true>, cudaFuncAttributeMaxDynamicSharedMemorySize, G_SMEM_DYN);
    cudaFuncSetAttribute(dft_split_hgemm,         cudaFuncAttributeMaxDynamicSharedMemorySize, DFT_SMEM_DYN);

    float* out_season = out + OFF_SEASON;
    float* out_growth = out + OFF_GROWTH;
    float* out_lvl    = out + OFF_LVL;

    // 1. fused prep (transpose/split + basis + weight f2h)
    prep_kernel<<<7680, 256>>>(res, (const float4*)Wi, (const float4*)Wo,
                               (const float4*)W1, (const float4*)W2);
    // 2. DFT on tensor cores (split-fp16, R8 config)
    dft_split_hgemm<<<dim3(4, 64), 256, DFT_SMEM_DYN>>>();
    // 3. top-16 per (b,d)
    topk_kernel<<<NBD/8, 256>>>();
    // 4. season + res1h
    season_kernel<<<dim3(32, 19), 256>>>(res, out_season);
    // 5. v = res1 @ Wi^T + bi  -> fp16
    hgemm<false,true,true><<<dim3(4, 64), 256, G_SMEM_DYN>>>(p_res1h, p_Wih, bi, nullptr, p_vh, NROW, 512, 512);
    // 6. growth EMA scan (fp16 v)
    growth_ema_scan<<<128, 256>>>(z0, v0_g, sw_g);
    // 7. growth = gr @ Wo^T + bo -> d_out (fp32)
    hgemm<false,true,false><<<dim3(4, 65), 256, G_SMEM_DYN>>>(p_gr, p_Woh, bo, out_growth, nullptr, NROWG, 512, 512);
    // 8. h1 = LN(res1 - growth[:,1:]) -> fp16
    ln_sub_kernel<<<NROW, 256>>>(out_growth, g1, b1);
    // 9. ffb = relu(h1 @ W1^T) -> fp16
    hgemm<true,false,true><<<dim3(16, 64), 256, G_SMEM_DYN>>>(p_h1h, p_W1h, nullptr, nullptr, p_ffb, NROW, DFFN, 512);
    // 10. ff2 = ffb @ W2^T -> fp16
    hgemm<false,false,true><<<dim3(4, 64), 256, G_SMEM_DYN>>>(p_ffb, p_W2h, nullptr, nullptr, p_ff2h, NROW, 512, DFFN);
    // 11. h = LN(h1 + ff2) -> d_out
    ln_add_kernel<<<NROW, 256>>>(g2, b2, out + OFF_H);
    // 12. gp/sp projections (4 rows/block)
    proj7_kernel<<<NROW/4, 256>>>(out_growth, out_season, Wg, bg, Ws, bs);
    // 13. level EMA (warp affine scan) -> d_out
    level_scan_kernel<<<(BB*COUTN*32 + 255)/256, 256>>>(level, sw_l, v0_l, out_lvl);
}